// round 9
// baseline (speedup 1.0000x reference)
#include <cuda_runtime.h>
#include <cuda_bf16.h>
#include <cstdint>
#include <math.h>

#define Sdim 256
#define Idim 512
#define Cdim 256
#define HD   256
#define SI   (Sdim*Idim)
#define P1_SS 8
#define XPITCH 264
#define APITCH 132
#define BPITCH 36

// ---------------- device scratch ----------------
__device__ float g_KV[(size_t)SI * 64];     // transposed: [i][t][j]  (i*Sdim+t)*64+j
__device__ float g_Xsum[Idim * Cdim];
__device__ float g_Qbar[Idim * HD];
__device__ float g_Wgt[Idim * HD];
// chunk-major packed bf16-pair weights: [(g*4+kc)*8192 + n*32 + kp]
__device__ uint32_t g_B32hi[2 * 4 * 8192];
__device__ uint32_t g_B32lo[2 * 4 * 8192];

__device__ __forceinline__ uint32_t pack_bf16(float a, float b) {
    __nv_bfloat162 t = __floats2bfloat162_rn(a, b);
    return *(uint32_t*)&t;
}
__device__ __forceinline__ uint32_t smem_u32(const void* p) {
    uint32_t a;
    asm("{ .reg .u64 t; cvta.to.shared.u64 t, %1; cvt.u32.u64 %0, t; }" : "=r"(a) : "l"(p));
    return a;
}
__device__ __forceinline__ void cp_async16(uint32_t saddr, const void* gptr) {
    asm volatile("cp.async.cg.shared.global [%0], [%1], 16;" :: "r"(saddr), "l"(gptr));
}
#define CP_COMMIT() asm volatile("cp.async.commit_group;" ::: "memory")
#define CP_WAIT0()  asm volatile("cp.async.wait_group 0;" ::: "memory")

// ---------------- prep: transpose + bf16 split + chunk-pack weights ----------------
__global__ void prep_weights_kernel(const float* __restrict__ Wg, const float* __restrict__ Wo) {
    int d = blockIdx.x * blockDim.x + threadIdx.x;
    if (d >= 65536) return;
    int n  = d & 255;
    int kp = (d >> 8) & 31;
    int kc = (d >> 13) & 3;
    int g  = d >> 15;
    const float* W = g ? Wo : Wg;
    int k0 = kc * 64 + kp * 2;
    float w0 = W[k0 * 256 + n], w1 = W[(k0 + 1) * 256 + n];
    __nv_bfloat16 h0 = __float2bfloat16(w0), h1 = __float2bfloat16(w1);
    float l0 = w0 - __bfloat162float(h0), l1 = w1 - __bfloat162float(h1);
    int idx = (g * 4 + kc) * 8192 + n * 32 + kp;
    g_B32hi[idx] = pack_bf16(__bfloat162float(h0), __bfloat162float(h1));
    g_B32lo[idx] = pack_bf16(l0, l1);
}

__global__ void zero_xsum_kernel() {
    int idx = blockIdx.x * blockDim.x + threadIdx.x;
    if (idx < Idim * Cdim) g_Xsum[idx] = 0.f;
}

// ================= pass 1: LN + K/V proj + xn column-sum =================
__device__ __forceinline__ void gemm_64x64x256(const float* __restrict__ a_s,
                                               const float* __restrict__ b_s,
                                               int tx, int ty, float acc[4][4]) {
#pragma unroll 2
    for (int k = 0; k < 256; k += 4) {
        float4 a0 = *(const float4*)(a_s + (ty * 4 + 0) * XPITCH + k);
        float4 a1 = *(const float4*)(a_s + (ty * 4 + 1) * XPITCH + k);
        float4 a2 = *(const float4*)(a_s + (ty * 4 + 2) * XPITCH + k);
        float4 a3 = *(const float4*)(a_s + (ty * 4 + 3) * XPITCH + k);
        float4 b0 = *(const float4*)(b_s + (k + 0) * 64 + tx * 4);
        float4 b1 = *(const float4*)(b_s + (k + 1) * 64 + tx * 4);
        float4 b2 = *(const float4*)(b_s + (k + 2) * 64 + tx * 4);
        float4 b3 = *(const float4*)(b_s + (k + 3) * 64 + tx * 4);
#define FMA_ROW(r, av, bv)                                        \
        acc[r][0] += (av) * (bv).x; acc[r][1] += (av) * (bv).y;   \
        acc[r][2] += (av) * (bv).z; acc[r][3] += (av) * (bv).w;
        FMA_ROW(0, a0.x, b0) FMA_ROW(0, a0.y, b1) FMA_ROW(0, a0.z, b2) FMA_ROW(0, a0.w, b3)
        FMA_ROW(1, a1.x, b0) FMA_ROW(1, a1.y, b1) FMA_ROW(1, a1.z, b2) FMA_ROW(1, a1.w, b3)
        FMA_ROW(2, a2.x, b0) FMA_ROW(2, a2.y, b1) FMA_ROW(2, a2.z, b2) FMA_ROW(2, a2.w, b3)
        FMA_ROW(3, a3.x, b0) FMA_ROW(3, a3.y, b1) FMA_ROW(3, a3.z, b2) FMA_ROW(3, a3.w, b3)
#undef FMA_ROW
    }
}

__device__ __forceinline__ void layernorm_tile(float* __restrict__ xs,
                                               const float* __restrict__ sgm,
                                               const float* __restrict__ sbt,
                                               float* __restrict__ xsum_s,
                                               int tid) {
    int w = tid >> 5, lane = tid & 31;
#pragma unroll
    for (int rr = 0; rr < 8; ++rr) {
        int r = w * 8 + rr;
        float vals[8];
        float sum = 0.f, sq = 0.f;
#pragma unroll
        for (int k = 0; k < 8; ++k) {
            float v = xs[r * XPITCH + lane + 32 * k];
            vals[k] = v; sum += v; sq += v * v;
        }
#pragma unroll
        for (int off = 16; off > 0; off >>= 1) {
            sum += __shfl_xor_sync(0xffffffffu, sum, off);
            sq  += __shfl_xor_sync(0xffffffffu, sq,  off);
        }
        float mu  = sum * (1.f / 256.f);
        float var = sq * (1.f / 256.f) - mu * mu;
        float rs  = rsqrtf(var + 1e-5f);
#pragma unroll
        for (int k = 0; k < 8; ++k) {
            int c = lane + 32 * k;
            float xn = (vals[k] - mu) * rs * sgm[c] + sbt[c];
            xs[r * XPITCH + c] = xn;
            if (xsum_s) xsum_s[r * 256 + c] += xn;
        }
    }
}

__global__ __launch_bounds__(256, 1)
void pass1_kernel(const float* __restrict__ x, const float* __restrict__ gamma,
                  const float* __restrict__ beta, const float* __restrict__ Wk,
                  const float* __restrict__ Wv) {
    extern __shared__ float sm[];
    float* xs     = sm;
    float* wkv    = xs + 64 * XPITCH;
    float* xsum_s = wkv + 256 * 64;
    float* sgm    = xsum_s + 64 * 256;
    float* sbt    = sgm + 256;

    const int tid = threadIdx.x;
    const int i0  = blockIdx.x * 64;
    const int s0  = blockIdx.y * P1_SS;
    const int tx  = tid & 15, ty = tid >> 4;
    const int sr0 = tid >> 6, sc4 = tid & 63;

    sgm[tid] = gamma[tid];
    sbt[tid] = beta[tid];
    for (int idx = tid; idx < 256 * 64; idx += 256) {
        int c = idx >> 6, j = idx & 63;
        wkv[idx] = (j < 32) ? Wk[c * 32 + j] : Wv[c * 32 + (j - 32)];
    }
    for (int idx = tid; idx < 64 * 256; idx += 256) xsum_s[idx] = 0.f;

    float4 xr[16];
    {
        const float* xrow = x + ((size_t)(s0 * Idim + i0)) * Cdim;
#pragma unroll
        for (int t = 0; t < 16; ++t) {
            int r = sr0 + t * 4;
            xr[t] = ((const float4*)(xrow + (size_t)r * Cdim))[sc4];
        }
    }
    __syncthreads();

    for (int ss = 0; ss < P1_SS; ++ss) {
        const int s = s0 + ss;
#pragma unroll
        for (int t = 0; t < 16; ++t) {
            int r = sr0 + t * 4;
            ((float4*)(xs + r * XPITCH))[sc4] = xr[t];
        }
        __syncthreads();
        if (ss + 1 < P1_SS) {
            const float* xrow = x + ((size_t)((s + 1) * Idim + i0)) * Cdim;
#pragma unroll
            for (int t = 0; t < 16; ++t) {
                int r = sr0 + t * 4;
                xr[t] = ((const float4*)(xrow + (size_t)r * Cdim))[sc4];
            }
        }
        layernorm_tile(xs, sgm, sbt, xsum_s, tid);
        __syncthreads();

        float acc[4][4] = {};
        gemm_64x64x256(xs, wkv, tx, ty, acc);

#pragma unroll
        for (int dr = 0; dr < 4; ++dr) {
            int r = ty * 4 + dr;
            float4 v = make_float4(acc[dr][0], acc[dr][1], acc[dr][2], acc[dr][3]);
            *(float4*)(g_KV + ((size_t)(i0 + r) * Sdim + s) * 64 + tx * 4) = v;
        }
        __syncthreads();
    }

    for (int idx = tid; idx < 64 * 256; idx += 256) {
        int r = idx >> 8, c = idx & 255;
        atomicAdd(&g_Xsum[(i0 + r) * 256 + c], xsum_s[idx]);
    }
}

// ================= pass 2q: Qbar = (Xsum/S) @ Wq (parallel n-tiles) =================
// grid (64, 4): 8 i-rows x 64 n-cols per block
__global__ __launch_bounds__(256, 1)
void pass2q_kernel(const float* __restrict__ Wq) {
    extern __shared__ float sm[];
    float* xbt = sm;            // 8*256
    float* wqs = sm + 2048;     // 256*64

    const int tid = threadIdx.x;
    const int i0 = blockIdx.x * 8, n0 = blockIdx.y * 64;

    for (int idx = tid; idx < 2048; idx += 256)
        xbt[idx] = g_Xsum[i0 * 256 + idx] * (1.f / (float)Sdim);
    for (int idx = tid; idx < 256 * 16; idx += 256) {
        int kk = idx >> 4, c4 = idx & 15;
        ((float4*)(wqs + kk * 64))[c4] = *(const float4*)(Wq + kk * 256 + n0 + c4 * 4);
    }
    __syncthreads();

    const int col = tid & 63, rr = tid >> 6;   // rows rr, rr+4
    float a0 = 0.f, a1 = 0.f;
#pragma unroll 8
    for (int kk = 0; kk < 256; ++kk) {
        float wv = wqs[kk * 64 + col];
        a0 += xbt[rr * 256 + kk] * wv;
        a1 += xbt[(rr + 4) * 256 + kk] * wv;
    }
    g_Qbar[(i0 + rr) * 256 + n0 + col] = a0;
    g_Qbar[(i0 + rr + 4) * 256 + n0 + col] = a1;
}

// ================= pass 2a: attention per column (coalesced KV) =================
#define KVP 65
__global__ __launch_bounds__(256, 1)
void pass2a_kernel() {
    extern __shared__ float sm[];
    float* qb  = sm;
    float* kvs = sm + 256;
    float* sc  = kvs + 256 * KVP;

    const int i = blockIdx.x, tid = threadIdx.x;
    qb[tid] = g_Qbar[i * 256 + tid];

    const float4* src = (const float4*)(g_KV + (size_t)i * Sdim * 64);
    for (int idx = tid; idx < 256 * 16; idx += 256) {
        int t = idx >> 4, j4 = idx & 15;
        float4 v = src[idx];
        float* d = kvs + t * KVP + j4 * 4;
        d[0] = v.x; d[1] = v.y; d[2] = v.z; d[3] = v.w;
    }
    __syncthreads();

    const int h = tid >> 5, lt = tid & 31;
    float sv[8];
#pragma unroll
    for (int k = 0; k < 8; ++k) {
        int t = lt + 32 * k;
        float s = 0.f;
#pragma unroll
        for (int d = 0; d < 32; ++d) s += qb[h * 32 + d] * kvs[t * KVP + d];
        sv[k] = s * 0.17677669529663687f;
    }
    float mx = sv[0];
#pragma unroll
    for (int k = 1; k < 8; ++k) mx = fmaxf(mx, sv[k]);
#pragma unroll
    for (int off = 16; off > 0; off >>= 1) mx = fmaxf(mx, __shfl_xor_sync(0xffffffffu, mx, off));
    float sum = 0.f;
#pragma unroll
    for (int k = 0; k < 8; ++k) { sv[k] = __expf(sv[k] - mx); sum += sv[k]; }
#pragma unroll
    for (int off = 16; off > 0; off >>= 1) sum += __shfl_xor_sync(0xffffffffu, sum, off);
    float rinv = 1.f / sum;
#pragma unroll
    for (int k = 0; k < 8; ++k) sc[h * 256 + lt + 32 * k] = sv[k] * rinv;
    __syncthreads();

    const int d = tid & 31;
    float wacc = 0.f;
#pragma unroll 4
    for (int t = 0; t < 256; ++t) wacc += sc[h * 256 + t] * kvs[t * KVP + 32 + d];
    g_Wgt[(size_t)i * 256 + h * 32 + d] = wacc;
}

// ================= pass 2b: mma.sync bf16x3, 512 threads, cp.async =================
#define SM_AH 1024
#define SM_AL 17920
#define SM_B  34816
#define SM2B_BYTES (53248 * 4)

__device__ __forceinline__ const uint4* chunk_src(int j) {
    int g = j >> 3, jj = j & 7, kc = jj >> 1;
    const uint32_t* base = (jj & 1) ? g_B32lo : g_B32hi;
    return (const uint4*)(base + (g * 4 + kc) * 8192);
}

__device__ __forceinline__ void mma_pass512(const uint32_t* __restrict__ A,
                                            const uint32_t* __restrict__ B,
                                            int kc, int m0, int n0, int gid, int tig,
                                            float acc[4][4][4]) {
#pragma unroll
    for (int s = 0; s < 4; ++s) {
        const int kpA = kc * 32 + s * 8 + tig;
        uint32_t a[4][4];
#pragma unroll
        for (int mi = 0; mi < 4; ++mi) {
            const uint32_t* Ar = A + (m0 + mi * 16 + gid) * APITCH + kpA;
            a[mi][0] = Ar[0];
            a[mi][1] = Ar[8 * APITCH];
            a[mi][2] = Ar[4];
            a[mi][3] = Ar[8 * APITCH + 4];
        }
#pragma unroll
        for (int ni = 0; ni < 4; ++ni) {
            const uint32_t* Br = B + (n0 + ni * 8 + gid) * BPITCH + s * 8 + tig;
            uint32_t b0 = Br[0], b1 = Br[4];
#pragma unroll
            for (int mi = 0; mi < 4; ++mi) {
                asm volatile(
                    "mma.sync.aligned.m16n8k16.row.col.f32.bf16.bf16.f32 "
                    "{%0,%1,%2,%3}, {%4,%5,%6,%7}, {%8,%9}, {%0,%1,%2,%3};"
                    : "+f"(acc[mi][ni][0]), "+f"(acc[mi][ni][1]),
                      "+f"(acc[mi][ni][2]), "+f"(acc[mi][ni][3])
                    : "r"(a[mi][0]), "r"(a[mi][1]), "r"(a[mi][2]), "r"(a[mi][3]),
                      "r"(b0), "r"(b1));
            }
        }
    }
}

__global__ __launch_bounds__(512, 1)
void pass2b_mma_kernel(const float* __restrict__ x, const float* __restrict__ gamma,
                       const float* __restrict__ beta, const float* __restrict__ bg,
                       const float* __restrict__ bo, float* __restrict__ out) {
    extern __shared__ uint32_t smu[];
    float* fsm = (float*)smu;
    const uint32_t sb_bytes = smem_u32(smu) + SM_B * 4;
    const int tid = threadIdx.x;
    const int wid = tid >> 5, lane = tid & 31;
    const int gid = lane >> 2, tig = lane & 3;
    const int m0 = (wid >> 3) * 64, n0 = (wid & 7) * 32;
    const size_t r0 = (size_t)blockIdx.x * 128;
    const int i0 = (int)(r0 % Idim);

    if (tid < 256) {
        fsm[tid] = gamma[tid];
        fsm[256 + tid] = beta[tid];
        fsm[512 + tid] = bg[tid];
        fsm[768 + tid] = bo[tid];
    }
    __syncthreads();

    // ---- LN: 4 threads per row (64 cols each) ----
    {
        const int r = tid >> 2, q = tid & 3;
        const float* xr = x + (r0 + r) * Cdim + q * 64;
        float sum = 0.f, sq = 0.f;
#pragma unroll 4
        for (int c = 0; c < 64; c += 4) {
            float4 v = *(const float4*)(xr + c);
            sum += v.x + v.y + v.z + v.w;
            sq  += v.x * v.x + v.y * v.y + v.z * v.z + v.w * v.w;
        }
        sum += __shfl_xor_sync(0xffffffffu, sum, 1);
        sq  += __shfl_xor_sync(0xffffffffu, sq, 1);
        sum += __shfl_xor_sync(0xffffffffu, sum, 2);
        sq  += __shfl_xor_sync(0xffffffffu, sq, 2);
        float mu  = sum * (1.f / 256.f);
        float var = sq * (1.f / 256.f) - mu * mu;
        float rs  = rsqrtf(var + 1e-5f);
        uint32_t* Ah = smu + SM_AH + r * APITCH + q * 32;
        uint32_t* Al = smu + SM_AL + r * APITCH + q * 32;
#pragma unroll 4
        for (int j4 = 0; j4 < 16; ++j4) {
            float4 v = *(const float4*)(xr + j4 * 4);
            int c = q * 64 + j4 * 4;
            float x0 = (v.x - mu) * rs * fsm[c + 0] + fsm[256 + c + 0];
            float x1 = (v.y - mu) * rs * fsm[c + 1] + fsm[256 + c + 1];
            float x2 = (v.z - mu) * rs * fsm[c + 2] + fsm[256 + c + 2];
            float x3 = (v.w - mu) * rs * fsm[c + 3] + fsm[256 + c + 3];
            float h0 = __bfloat162float(__float2bfloat16(x0));
            float h1 = __bfloat162float(__float2bfloat16(x1));
            float h2 = __bfloat162float(__float2bfloat16(x2));
            float h3 = __bfloat162float(__float2bfloat16(x3));
            Ah[j4 * 2 + 0] = pack_bf16(h0, h1);
            Ah[j4 * 2 + 1] = pack_bf16(h2, h3);
            Al[j4 * 2 + 0] = pack_bf16(x0 - h0, x1 - h1);
            Al[j4 * 2 + 1] = pack_bf16(x2 - h2, x3 - h3);
        }
    }

    // ---- stage chunk 0 via cp.async ----
    {
        const uint4* s = chunk_src(0);
#pragma unroll
        for (int t = 0; t < 4; ++t) {
            int u = tid + t * 512;
            int n = u >> 3, kq = u & 7;
            cp_async16(sb_bytes + (uint32_t)(n * 9 + kq) * 16, s + u);
        }
        CP_COMMIT(); CP_WAIT0();
    }
    __syncthreads();

    float acc[4][4][4] = {};
    int cur = 0;

    for (int j = 0; j < 16; ++j) {
        if (j < 15) {
            const uint4* s = chunk_src(j + 1);
            uint32_t dstb = sb_bytes + (uint32_t)(cur ^ 1) * 9216 * 4;
#pragma unroll
            for (int t = 0; t < 4; ++t) {
                int u = tid + t * 512;
                int n = u >> 3, kq = u & 7;
                cp_async16(dstb + (uint32_t)(n * 9 + kq) * 16, s + u);
            }
            CP_COMMIT();
        }
        const int jj = j & 7, kc = jj >> 1;
        const bool hi = !(jj & 1);
        const uint32_t* Bb = smu + SM_B + cur * 9216;
        mma_pass512(smu + SM_AH, Bb, kc, m0, n0, gid, tig, acc);
        if (hi) mma_pass512(smu + SM_AL, Bb, kc, m0, n0, gid, tig, acc);
        if (j < 15) CP_WAIT0();
        __syncthreads();
        cur ^= 1;

        if (j == 7) {
            // ---- epilogue 1: val = sigmoid(acc + bg) * wgt -> A (bf16 hi/lo) ----
#pragma unroll
            for (int mi = 0; mi < 4; ++mi) {
#pragma unroll
                for (int ni = 0; ni < 4; ++ni) {
                    int c = n0 + ni * 8 + tig * 2;
#pragma unroll
                    for (int half = 0; half < 2; ++half) {
                        int r = m0 + mi * 16 + gid + half * 8;
                        float2 w = *(const float2*)(g_Wgt + (size_t)(i0 + r) * 256 + c);
                        float t0 = acc[mi][ni][half * 2 + 0] + fsm[512 + c];
                        float t1 = acc[mi][ni][half * 2 + 1] + fsm[512 + c + 1];
                        float v0 = w.x / (1.f + __expf(-t0));
                        float v1 = w.y / (1.f + __expf(-t1));
                        float h0 = __bfloat162float(__float2bfloat16(v0));
                        float h1 = __bfloat162float(__float2bfloat16(v1));
                        smu[SM_AH + r * APITCH + (c >> 1)] = pack_bf16(h0, h1);
                        smu[SM_AL + r * APITCH + (c >> 1)] = pack_bf16(v0 - h0, v1 - h1);
                        acc[mi][ni][half * 2 + 0] = 0.f;
                        acc[mi][ni][half * 2 + 1] = 0.f;
                    }
                }
            }
            __syncthreads();
        }
    }

    // ---- epilogue 2: out = acc + bo ----
#pragma unroll
    for (int mi = 0; mi < 4; ++mi) {
#pragma unroll
        for (int ni = 0; ni < 4; ++ni) {
            int c = n0 + ni * 8 + tig * 2;
#pragma unroll
            for (int half = 0; half < 2; ++half) {
                int r = m0 + mi * 16 + gid + half * 8;
                float2 v;
                v.x = acc[mi][ni][half * 2 + 0] + fsm[768 + c];
                v.y = acc[mi][ni][half * 2 + 1] + fsm[768 + c + 1];
                *(float2*)(out + (r0 + r) * Cdim + c) = v;
            }
        }
    }
}

// ---------------- launch ----------------
extern "C" void kernel_launch(void* const* d_in, const int* in_sizes, int n_in,
                              void* d_out, int out_size) {
    const float* x     = (const float*)d_in[0];
    const float* gamma = (const float*)d_in[1];
    const float* beta  = (const float*)d_in[2];
    const float* Wq    = (const float*)d_in[3];
    const float* Wk    = (const float*)d_in[4];
    const float* Wv    = (const float*)d_in[5];
    const float* Wg    = (const float*)d_in[6];
    const float* bg    = (const float*)d_in[7];
    const float* Wo    = (const float*)d_in[8];
    const float* bo    = (const float*)d_in[9];
    float* out = (float*)d_out;

    const int SMEM1  = (64 * XPITCH + 256 * 64 + 64 * 256 + 512) * 4;
    const int SMEM2Q = (2048 + 256 * 64) * 4;
    const int SMEM2A = (256 + 256 * KVP + 8 * 256) * 4;

    cudaFuncSetAttribute(pass1_kernel,      cudaFuncAttributeMaxDynamicSharedMemorySize, SMEM1);
    cudaFuncSetAttribute(pass2q_kernel,     cudaFuncAttributeMaxDynamicSharedMemorySize, SMEM2Q);
    cudaFuncSetAttribute(pass2a_kernel,     cudaFuncAttributeMaxDynamicSharedMemorySize, SMEM2A);
    cudaFuncSetAttribute(pass2b_mma_kernel, cudaFuncAttributeMaxDynamicSharedMemorySize, SM2B_BYTES);

    zero_xsum_kernel<<<(Idim * Cdim + 255) / 256, 256>>>();
    prep_weights_kernel<<<256, 256>>>(Wg, Wo);
    pass1_kernel<<<dim3(Idim / 64, Sdim / P1_SS), 256, SMEM1>>>(x, gamma, beta, Wk, Wv);
    pass2q_kernel<<<dim3(64, 4), 256, SMEM2Q>>>(Wq);
    pass2a_kernel<<<Idim, 256, SMEM2A>>>();
    pass2b_mma_kernel<<<SI / 128, 512, SM2B_BYTES>>>(x, gamma, beta, bg, bo, out);
}

// round 10
// speedup vs baseline: 1.1847x; 1.1847x over previous
#include <cuda_runtime.h>
#include <cuda_bf16.h>
#include <cuda_fp16.h>
#include <cstdint>
#include <math.h>

#define Sdim 256
#define Idim 512
#define Cdim 256
#define HD   256
#define SI   (Sdim*Idim)
#define P1_SS 8
#define XPITCH 264
#define APITCH 132
#define BPITCH 36

// ---------------- device scratch ----------------
__device__ float g_KV[(size_t)SI * 64];     // transposed: [i][t][j]  (i*Sdim+t)*64+j
__device__ float g_Xsum[Idim * Cdim];
__device__ float g_Qbar[Idim * HD];
__device__ float g_Wgt[Idim * HD];
// chunk-major packed fp16-pair weights: [(g*4+kc)*8192 + n*32 + kp]
__device__ uint32_t g_B32hi[2 * 4 * 8192];
__device__ uint32_t g_B32lo[2 * 4 * 8192];

__device__ __forceinline__ uint32_t pack_f16(float a, float b) {
    __half2 t = __floats2half2_rn(a, b);
    return *(uint32_t*)&t;
}

// ---------------- prep: transpose + fp16 split + chunk-pack weights ----------------
__global__ void prep_weights_kernel(const float* __restrict__ Wg, const float* __restrict__ Wo) {
    int d = blockIdx.x * blockDim.x + threadIdx.x;
    if (d >= 65536) return;
    int n  = d & 255;
    int kp = (d >> 8) & 31;
    int kc = (d >> 13) & 3;
    int g  = d >> 15;
    const float* W = g ? Wo : Wg;
    int k0 = kc * 64 + kp * 2;
    float w0 = W[k0 * 256 + n], w1 = W[(k0 + 1) * 256 + n];
    __half h0 = __float2half_rn(w0), h1 = __float2half_rn(w1);
    float l0 = w0 - __half2float(h0), l1 = w1 - __half2float(h1);
    int idx = (g * 4 + kc) * 8192 + n * 32 + kp;
    g_B32hi[idx] = pack_f16(__half2float(h0), __half2float(h1));
    g_B32lo[idx] = pack_f16(l0, l1);
}

__global__ void zero_xsum_kernel() {
    int idx = blockIdx.x * blockDim.x + threadIdx.x;
    if (idx < Idim * Cdim) g_Xsum[idx] = 0.f;
}

// ================= pass 1: LN + K/V proj + xn column-sum =================
__device__ __forceinline__ void gemm_64x64x256(const float* __restrict__ a_s,
                                               const float* __restrict__ b_s,
                                               int tx, int ty, float acc[4][4]) {
#pragma unroll 2
    for (int k = 0; k < 256; k += 4) {
        float4 a0 = *(const float4*)(a_s + (ty * 4 + 0) * XPITCH + k);
        float4 a1 = *(const float4*)(a_s + (ty * 4 + 1) * XPITCH + k);
        float4 a2 = *(const float4*)(a_s + (ty * 4 + 2) * XPITCH + k);
        float4 a3 = *(const float4*)(a_s + (ty * 4 + 3) * XPITCH + k);
        float4 b0 = *(const float4*)(b_s + (k + 0) * 64 + tx * 4);
        float4 b1 = *(const float4*)(b_s + (k + 1) * 64 + tx * 4);
        float4 b2 = *(const float4*)(b_s + (k + 2) * 64 + tx * 4);
        float4 b3 = *(const float4*)(b_s + (k + 3) * 64 + tx * 4);
#define FMA_ROW(r, av, bv)                                        \
        acc[r][0] += (av) * (bv).x; acc[r][1] += (av) * (bv).y;   \
        acc[r][2] += (av) * (bv).z; acc[r][3] += (av) * (bv).w;
        FMA_ROW(0, a0.x, b0) FMA_ROW(0, a0.y, b1) FMA_ROW(0, a0.z, b2) FMA_ROW(0, a0.w, b3)
        FMA_ROW(1, a1.x, b0) FMA_ROW(1, a1.y, b1) FMA_ROW(1, a1.z, b2) FMA_ROW(1, a1.w, b3)
        FMA_ROW(2, a2.x, b0) FMA_ROW(2, a2.y, b1) FMA_ROW(2, a2.z, b2) FMA_ROW(2, a2.w, b3)
        FMA_ROW(3, a3.x, b0) FMA_ROW(3, a3.y, b1) FMA_ROW(3, a3.z, b2) FMA_ROW(3, a3.w, b3)
#undef FMA_ROW
    }
}

__device__ __forceinline__ void layernorm_tile(float* __restrict__ xs,
                                               const float* __restrict__ sgm,
                                               const float* __restrict__ sbt,
                                               float* __restrict__ xsum_s,
                                               int tid) {
    int w = tid >> 5, lane = tid & 31;
#pragma unroll
    for (int rr = 0; rr < 8; ++rr) {
        int r = w * 8 + rr;
        float vals[8];
        float sum = 0.f, sq = 0.f;
#pragma unroll
        for (int k = 0; k < 8; ++k) {
            float v = xs[r * XPITCH + lane + 32 * k];
            vals[k] = v; sum += v; sq += v * v;
        }
#pragma unroll
        for (int off = 16; off > 0; off >>= 1) {
            sum += __shfl_xor_sync(0xffffffffu, sum, off);
            sq  += __shfl_xor_sync(0xffffffffu, sq,  off);
        }
        float mu  = sum * (1.f / 256.f);
        float var = sq * (1.f / 256.f) - mu * mu;
        float rs  = rsqrtf(var + 1e-5f);
#pragma unroll
        for (int k = 0; k < 8; ++k) {
            int c = lane + 32 * k;
            float xn = (vals[k] - mu) * rs * sgm[c] + sbt[c];
            xs[r * XPITCH + c] = xn;
            if (xsum_s) xsum_s[r * 256 + c] += xn;
        }
    }
}

__global__ __launch_bounds__(256, 1)
void pass1_kernel(const float* __restrict__ x, const float* __restrict__ gamma,
                  const float* __restrict__ beta, const float* __restrict__ Wk,
                  const float* __restrict__ Wv) {
    extern __shared__ float sm[];
    float* xs     = sm;
    float* wkv    = xs + 64 * XPITCH;
    float* xsum_s = wkv + 256 * 64;
    float* sgm    = xsum_s + 64 * 256;
    float* sbt    = sgm + 256;

    const int tid = threadIdx.x;
    const int i0  = blockIdx.x * 64;
    const int s0  = blockIdx.y * P1_SS;
    const int tx  = tid & 15, ty = tid >> 4;
    const int sr0 = tid >> 6, sc4 = tid & 63;

    sgm[tid] = gamma[tid];
    sbt[tid] = beta[tid];
    for (int idx = tid; idx < 256 * 64; idx += 256) {
        int c = idx >> 6, j = idx & 63;
        wkv[idx] = (j < 32) ? Wk[c * 32 + j] : Wv[c * 32 + (j - 32)];
    }
    for (int idx = tid; idx < 64 * 256; idx += 256) xsum_s[idx] = 0.f;

    float4 xr[16];
    {
        const float* xrow = x + ((size_t)(s0 * Idim + i0)) * Cdim;
#pragma unroll
        for (int t = 0; t < 16; ++t) {
            int r = sr0 + t * 4;
            xr[t] = ((const float4*)(xrow + (size_t)r * Cdim))[sc4];
        }
    }
    __syncthreads();

    for (int ss = 0; ss < P1_SS; ++ss) {
        const int s = s0 + ss;
#pragma unroll
        for (int t = 0; t < 16; ++t) {
            int r = sr0 + t * 4;
            ((float4*)(xs + r * XPITCH))[sc4] = xr[t];
        }
        __syncthreads();
        if (ss + 1 < P1_SS) {
            const float* xrow = x + ((size_t)((s + 1) * Idim + i0)) * Cdim;
#pragma unroll
            for (int t = 0; t < 16; ++t) {
                int r = sr0 + t * 4;
                xr[t] = ((const float4*)(xrow + (size_t)r * Cdim))[sc4];
            }
        }
        layernorm_tile(xs, sgm, sbt, xsum_s, tid);
        __syncthreads();

        float acc[4][4] = {};
        gemm_64x64x256(xs, wkv, tx, ty, acc);

#pragma unroll
        for (int dr = 0; dr < 4; ++dr) {
            int r = ty * 4 + dr;
            float4 v = make_float4(acc[dr][0], acc[dr][1], acc[dr][2], acc[dr][3]);
            *(float4*)(g_KV + ((size_t)(i0 + r) * Sdim + s) * 64 + tx * 4) = v;
        }
        __syncthreads();
    }

    for (int idx = tid; idx < 64 * 256; idx += 256) {
        int r = idx >> 8, c = idx & 255;
        atomicAdd(&g_Xsum[(i0 + r) * 256 + c], xsum_s[idx]);
    }
}

// ================= pass 2q: Qbar = (Xsum/S) @ Wq (parallel n-tiles) =================
__global__ __launch_bounds__(256, 1)
void pass2q_kernel(const float* __restrict__ Wq) {
    extern __shared__ float sm[];
    float* xbt = sm;            // 8*256
    float* wqs = sm + 2048;     // 256*64

    const int tid = threadIdx.x;
    const int i0 = blockIdx.x * 8, n0 = blockIdx.y * 64;

    for (int idx = tid; idx < 2048; idx += 256)
        xbt[idx] = g_Xsum[i0 * 256 + idx] * (1.f / (float)Sdim);
    for (int idx = tid; idx < 256 * 16; idx += 256) {
        int kk = idx >> 4, c4 = idx & 15;
        ((float4*)(wqs + kk * 64))[c4] = *(const float4*)(Wq + kk * 256 + n0 + c4 * 4);
    }
    __syncthreads();

    const int col = tid & 63, rr = tid >> 6;
    float a0 = 0.f, a1 = 0.f;
#pragma unroll 8
    for (int kk = 0; kk < 256; ++kk) {
        float wv = wqs[kk * 64 + col];
        a0 += xbt[rr * 256 + kk] * wv;
        a1 += xbt[(rr + 4) * 256 + kk] * wv;
    }
    g_Qbar[(i0 + rr) * 256 + n0 + col] = a0;
    g_Qbar[(i0 + rr + 4) * 256 + n0 + col] = a1;
}

// ================= pass 2a: attention per column (coalesced KV) =================
#define KVP 65
__global__ __launch_bounds__(256, 1)
void pass2a_kernel() {
    extern __shared__ float sm[];
    float* qb  = sm;
    float* kvs = sm + 256;
    float* sc  = kvs + 256 * KVP;

    const int i = blockIdx.x, tid = threadIdx.x;
    qb[tid] = g_Qbar[i * 256 + tid];

    const float4* src = (const float4*)(g_KV + (size_t)i * Sdim * 64);
    for (int idx = tid; idx < 256 * 16; idx += 256) {
        int t = idx >> 4, j4 = idx & 15;
        float4 v = src[idx];
        float* d = kvs + t * KVP + j4 * 4;
        d[0] = v.x; d[1] = v.y; d[2] = v.z; d[3] = v.w;
    }
    __syncthreads();

    const int h = tid >> 5, lt = tid & 31;
    float sv[8];
#pragma unroll
    for (int k = 0; k < 8; ++k) {
        int t = lt + 32 * k;
        float s = 0.f;
#pragma unroll
        for (int d = 0; d < 32; ++d) s += qb[h * 32 + d] * kvs[t * KVP + d];
        sv[k] = s * 0.17677669529663687f;
    }
    float mx = sv[0];
#pragma unroll
    for (int k = 1; k < 8; ++k) mx = fmaxf(mx, sv[k]);
#pragma unroll
    for (int off = 16; off > 0; off >>= 1) mx = fmaxf(mx, __shfl_xor_sync(0xffffffffu, mx, off));
    float sum = 0.f;
#pragma unroll
    for (int k = 0; k < 8; ++k) { sv[k] = __expf(sv[k] - mx); sum += sv[k]; }
#pragma unroll
    for (int off = 16; off > 0; off >>= 1) sum += __shfl_xor_sync(0xffffffffu, sum, off);
    float rinv = 1.f / sum;
#pragma unroll
    for (int k = 0; k < 8; ++k) sc[h * 256 + lt + 32 * k] = sv[k] * rinv;
    __syncthreads();

    const int d = tid & 31;
    float wacc = 0.f;
#pragma unroll 4
    for (int t = 0; t < 256; ++t) wacc += sc[h * 256 + t] * kvs[t * KVP + 32 + d];
    g_Wgt[(size_t)i * 256 + h * 32 + d] = wacc;
}

// ================= pass 2b: mma.sync fp16 2-pass (LN + Wg GEMM + gate + Wo GEMM) =================
// smem layout (u32 index):
//   0: sgm[256], 256: sbt[256], 512: sbg[256], 768: sbo[256]
//   1024:  A [128][APITCH] fp16 pairs (16896 u32)
//   17920: Bbuf0 [256][BPITCH] (9216 u32)
//   27136: Bbuf1
#define SM_AH 1024
#define SM_B  17920
#define SM2B_BYTES ((17920 + 2 * 9216) * 4)

__device__ __forceinline__ const uint4* chunk_src(int j) {
    int g = j >> 3, jj = j & 7, kc = jj >> 1;
    const uint32_t* base = (jj & 1) ? g_B32lo : g_B32hi;
    return (const uint4*)(base + (g * 4 + kc) * 8192);
}

__device__ __forceinline__ void mma_pass(const uint32_t* __restrict__ A,
                                         const uint32_t* __restrict__ B,
                                         int kc, int m0, int n0, int gid, int tig,
                                         float acc[4][8][4]) {
#pragma unroll
    for (int s = 0; s < 4; ++s) {
        const int kpA = kc * 32 + s * 8 + tig;
        uint32_t a[4][4];
#pragma unroll
        for (int mi = 0; mi < 4; ++mi) {
            const uint32_t* Ar = A + (m0 + mi * 16 + gid) * APITCH + kpA;
            a[mi][0] = Ar[0];
            a[mi][1] = Ar[8 * APITCH];
            a[mi][2] = Ar[4];
            a[mi][3] = Ar[8 * APITCH + 4];
        }
#pragma unroll
        for (int ni = 0; ni < 8; ++ni) {
            const uint32_t* Br = B + (n0 + ni * 8 + gid) * BPITCH + s * 8 + tig;
            uint32_t b0 = Br[0], b1 = Br[4];
#pragma unroll
            for (int mi = 0; mi < 4; ++mi) {
                asm volatile(
                    "mma.sync.aligned.m16n8k16.row.col.f32.f16.f16.f32 "
                    "{%0,%1,%2,%3}, {%4,%5,%6,%7}, {%8,%9}, {%0,%1,%2,%3};"
                    : "+f"(acc[mi][ni][0]), "+f"(acc[mi][ni][1]),
                      "+f"(acc[mi][ni][2]), "+f"(acc[mi][ni][3])
                    : "r"(a[mi][0]), "r"(a[mi][1]), "r"(a[mi][2]), "r"(a[mi][3]),
                      "r"(b0), "r"(b1));
            }
        }
    }
}

__global__ __launch_bounds__(256, 1)
void pass2b_mma_kernel(const float* __restrict__ x, const float* __restrict__ gamma,
                       const float* __restrict__ beta, const float* __restrict__ bg,
                       const float* __restrict__ bo, float* __restrict__ out) {
    extern __shared__ uint32_t smu[];
    float* fsm = (float*)smu;
    const int tid = threadIdx.x;
    const int wid = tid >> 5, lane = tid & 31;
    const int gid = lane >> 2, tig = lane & 3;
    const int m0 = (wid >> 2) * 64, n0 = (wid & 3) * 64;
    const size_t r0 = (size_t)blockIdx.x * 128;
    const int i0 = (int)(r0 % Idim);

    fsm[tid] = gamma[tid];
    fsm[256 + tid] = beta[tid];
    fsm[512 + tid] = bg[tid];
    fsm[768 + tid] = bo[tid];
    __syncthreads();

    // ---- LN: two threads per row; normalize + pack fp16 ----
    {
        const int r = tid >> 1, cb = (tid & 1) * 128;
        const float* xr = x + (r0 + r) * Cdim + cb;
        float sum = 0.f, sq = 0.f;
#pragma unroll 8
        for (int c = 0; c < 128; c += 4) {
            float4 v = *(const float4*)(xr + c);
            sum += v.x + v.y + v.z + v.w;
            sq  += v.x * v.x + v.y * v.y + v.z * v.z + v.w * v.w;
        }
        sum += __shfl_xor_sync(0xffffffffu, sum, 1);
        sq  += __shfl_xor_sync(0xffffffffu, sq, 1);
        float mu  = sum * (1.f / 256.f);
        float var = sq * (1.f / 256.f) - mu * mu;
        float rs  = rsqrtf(var + 1e-5f);
        uint32_t* Ah = smu + SM_AH + r * APITCH + (cb >> 1);
#pragma unroll 4
        for (int j4 = 0; j4 < 32; ++j4) {
            float4 v = *(const float4*)(xr + j4 * 4);
            int c = cb + j4 * 4;
            float x0 = (v.x - mu) * rs * fsm[c + 0] + fsm[256 + c + 0];
            float x1 = (v.y - mu) * rs * fsm[c + 1] + fsm[256 + c + 1];
            float x2 = (v.z - mu) * rs * fsm[c + 2] + fsm[256 + c + 2];
            float x3 = (v.w - mu) * rs * fsm[c + 3] + fsm[256 + c + 3];
            Ah[j4 * 2 + 0] = pack_f16(x0, x1);
            Ah[j4 * 2 + 1] = pack_f16(x2, x3);
        }
    }

    // ---- stage chunk 0 ----
    {
        const uint4* s = chunk_src(0);
        uint4* d = (uint4*)(smu + SM_B);
#pragma unroll
        for (int t = 0; t < 8; ++t) {
            int u = tid + t * 256;
            int n = u >> 3, kq = u & 7;
            d[n * 9 + kq] = s[u];
        }
    }
    __syncthreads();

    float acc[4][8][4] = {};
    int cur = 0;

    for (int j = 0; j < 16; ++j) {
        uint4 pf[8];
        if (j < 15) {
            const uint4* s = chunk_src(j + 1);
#pragma unroll
            for (int t = 0; t < 8; ++t) pf[t] = s[tid + t * 256];
        }
        const int kc = (j & 7) >> 1;
        const uint32_t* Bb = smu + SM_B + cur * 9216;
        mma_pass(smu + SM_AH, Bb, kc, m0, n0, gid, tig, acc);
        if (j < 15) {
            uint4* d = (uint4*)(smu + SM_B + (cur ^ 1) * 9216);
#pragma unroll
            for (int t = 0; t < 8; ++t) {
                int u = tid + t * 256;
                int n = u >> 3, kq = u & 7;
                d[n * 9 + kq] = pf[t];
            }
        }
        __syncthreads();
        cur ^= 1;

        if (j == 7) {
            // ---- epilogue 1: val = sigmoid(acc + bg) * wgt -> A (fp16) ----
#pragma unroll
            for (int mi = 0; mi < 4; ++mi) {
#pragma unroll
                for (int ni = 0; ni < 8; ++ni) {
                    int c = n0 + ni * 8 + tig * 2;
#pragma unroll
                    for (int half = 0; half < 2; ++half) {
                        int r = m0 + mi * 16 + gid + half * 8;
                        float2 w = *(const float2*)(g_Wgt + (size_t)(i0 + r) * 256 + c);
                        float t0 = acc[mi][ni][half * 2 + 0] + fsm[512 + c];
                        float t1 = acc[mi][ni][half * 2 + 1] + fsm[512 + c + 1];
                        float v0 = w.x / (1.f + __expf(-t0));
                        float v1 = w.y / (1.f + __expf(-t1));
                        smu[SM_AH + r * APITCH + (c >> 1)] = pack_f16(v0, v1);
                        acc[mi][ni][half * 2 + 0] = 0.f;
                        acc[mi][ni][half * 2 + 1] = 0.f;
                    }
                }
            }
            __syncthreads();
        }
    }

    // ---- epilogue 2: out = acc + bo ----
#pragma unroll
    for (int mi = 0; mi < 4; ++mi) {
#pragma unroll
        for (int ni = 0; ni < 8; ++ni) {
            int c = n0 + ni * 8 + tig * 2;
#pragma unroll
            for (int half = 0; half < 2; ++half) {
                int r = m0 + mi * 16 + gid + half * 8;
                float2 v;
                v.x = acc[mi][ni][half * 2 + 0] + fsm[768 + c];
                v.y = acc[mi][ni][half * 2 + 1] + fsm[768 + c + 1];
                *(float2*)(out + (r0 + r) * Cdim + c) = v;
            }
        }
    }
}

// ---------------- launch ----------------
extern "C" void kernel_launch(void* const* d_in, const int* in_sizes, int n_in,
                              void* d_out, int out_size) {
    const float* x     = (const float*)d_in[0];
    const float* gamma = (const float*)d_in[1];
    const float* beta  = (const float*)d_in[2];
    const float* Wq    = (const float*)d_in[3];
    const float* Wk    = (const float*)d_in[4];
    const float* Wv    = (const float*)d_in[5];
    const float* Wg    = (const float*)d_in[6];
    const float* bg    = (const float*)d_in[7];
    const float* Wo    = (const float*)d_in[8];
    const float* bo    = (const float*)d_in[9];
    float* out = (float*)d_out;

    const int SMEM1  = (64 * XPITCH + 256 * 64 + 64 * 256 + 512) * 4;
    const int SMEM2Q = (2048 + 256 * 64) * 4;
    const int SMEM2A = (256 + 256 * KVP + 8 * 256) * 4;

    cudaFuncSetAttribute(pass1_kernel,      cudaFuncAttributeMaxDynamicSharedMemorySize, SMEM1);
    cudaFuncSetAttribute(pass2q_kernel,     cudaFuncAttributeMaxDynamicSharedMemorySize, SMEM2Q);
    cudaFuncSetAttribute(pass2a_kernel,     cudaFuncAttributeMaxDynamicSharedMemorySize, SMEM2A);
    cudaFuncSetAttribute(pass2b_mma_kernel, cudaFuncAttributeMaxDynamicSharedMemorySize, SM2B_BYTES);

    zero_xsum_kernel<<<(Idim * Cdim + 255) / 256, 256>>>();
    prep_weights_kernel<<<256, 256>>>(Wg, Wo);
    pass1_kernel<<<dim3(Idim / 64, Sdim / P1_SS), 256, SMEM1>>>(x, gamma, beta, Wk, Wv);
    pass2q_kernel<<<dim3(64, 4), 256, SMEM2Q>>>(Wq);
    pass2a_kernel<<<Idim, 256, SMEM2A>>>();
    pass2b_mma_kernel<<<SI / 128, 256, SM2B_BYTES>>>(x, gamma, beta, bg, bo, out);
}

// round 11
// speedup vs baseline: 1.3821x; 1.1666x over previous
#include <cuda_runtime.h>
#include <cuda_bf16.h>
#include <cuda_fp16.h>
#include <cstdint>
#include <math.h>

#define Sdim 256
#define Idim 512
#define Cdim 256
#define HD   256
#define SI   (Sdim*Idim)
#define APITCH 132
#define BPITCH 36

// ---------------- device scratch ----------------
__device__ float g_KV[(size_t)SI * 64];     // transposed: [i][t][j]  (i*Sdim+t)*64+j
__device__ float g_Xsum[Idim * Cdim];
__device__ float g_Qbar[Idim * HD];
__device__ float g_Wgt[Idim * HD];
// chunk-major packed fp16-pair weights: [(g*4+kc)*8192 + n*32 + kp]
__device__ uint32_t g_B32hi[2 * 4 * 8192];
__device__ uint32_t g_B32lo[2 * 4 * 8192];
// Wkv fp16 pairs: [n (0..63)][kp (0..127)]
__device__ uint32_t g_KVW32hi[64 * 128];
__device__ uint32_t g_KVW32lo[64 * 128];

__device__ __forceinline__ uint32_t pack_f16(float a, float b) {
    __half2 t = __floats2half2_rn(a, b);
    return *(uint32_t*)&t;
}

// ---------------- prep: Wg/Wo fp16 split + Xsum zero ----------------
__global__ void prep_weights_kernel(const float* __restrict__ Wg, const float* __restrict__ Wo) {
    int d = blockIdx.x * blockDim.x + threadIdx.x;
    if (d >= 65536) return;
    g_Xsum[d] = 0.f;
    g_Xsum[d + 65536] = 0.f;
    int n  = d & 255;
    int kp = (d >> 8) & 31;
    int kc = (d >> 13) & 3;
    int g  = d >> 15;
    const float* W = g ? Wo : Wg;
    int k0 = kc * 64 + kp * 2;
    float w0 = W[k0 * 256 + n], w1 = W[(k0 + 1) * 256 + n];
    __half h0 = __float2half_rn(w0), h1 = __float2half_rn(w1);
    float l0 = w0 - __half2float(h0), l1 = w1 - __half2float(h1);
    int idx = (g * 4 + kc) * 8192 + n * 32 + kp;
    g_B32hi[idx] = pack_f16(__half2float(h0), __half2float(h1));
    g_B32lo[idx] = pack_f16(l0, l1);
}

// ---------------- prep: Wk|Wv fp16 split, [n][kp] pair-major ----------------
__global__ void prep_kv_kernel(const float* __restrict__ Wk, const float* __restrict__ Wv) {
    int d = blockIdx.x * blockDim.x + threadIdx.x;
    if (d >= 64 * 128) return;
    int n = d >> 7, kp = d & 127;
    int k0 = kp * 2;
    float w0 = (n < 32) ? Wk[k0 * 32 + n] : Wv[k0 * 32 + (n - 32)];
    float w1 = (n < 32) ? Wk[(k0 + 1) * 32 + n] : Wv[(k0 + 1) * 32 + (n - 32)];
    __half h0 = __float2half_rn(w0), h1 = __float2half_rn(w1);
    g_KVW32hi[d] = pack_f16(__half2float(h0), __half2float(h1));
    g_KVW32lo[d] = pack_f16(w0 - __half2float(h0), w1 - __half2float(h1));
}

// ================= pass 1: LN + K/V proj via mma + xn column-sum =================
// grid (Idim/64, Sdim/8), 256 threads. smem (u32):
//   0: sgm[256], 256: sbt[256], 512: xnh[64*132], 9  -> bh, bl
#define P1_XNH 512
#define P1_BH  (512 + 64 * 132)
#define P1_BL  (P1_BH + 64 * 132)
#define P1_SMEM_U32 (P1_BL + 64 * 132)

__global__ __launch_bounds__(256, 1)
void pass1_kernel(const float* __restrict__ x, const float* __restrict__ gamma,
                  const float* __restrict__ beta) {
    extern __shared__ uint32_t smu[];
    float* fsm = (float*)smu;
    const int tid = threadIdx.x;
    const int wid = tid >> 5, lane = tid & 31;
    const int gid = lane >> 2, tig = lane & 3;
    const int mw = wid >> 1, nw = wid & 1;        // warp tile: 16 rows x 32 cols
    const int m0w = mw * 16, n0w = nw * 32;
    const int i0 = blockIdx.x * 64, s0 = blockIdx.y * 8;
    const int r = tid >> 2, q = tid & 3;          // LN: 4 threads per row

    fsm[tid] = gamma[tid];
    fsm[256 + tid] = beta[tid];
    for (int idx = tid; idx < 8192; idx += 256) {
        int n = idx >> 7, kp = idx & 127;
        smu[P1_BH + n * 132 + kp] = g_KVW32hi[idx];
        smu[P1_BL + n * 132 + kp] = g_KVW32lo[idx];
    }

    float xa[64];
#pragma unroll
    for (int j = 0; j < 64; ++j) xa[j] = 0.f;
    __syncthreads();

    for (int ss = 0; ss < 8; ++ss) {
        const int s = s0 + ss;
        const float* xr = x + ((size_t)(s * Idim + i0 + r)) * Cdim;

        // ---- LN: cols 8j+2q(+1), j=0..31 ----
        float sum = 0.f, sq = 0.f;
#pragma unroll 8
        for (int j = 0; j < 32; ++j) {
            float2 v = *(const float2*)(xr + 8 * j + 2 * q);
            sum += v.x + v.y;
            sq  += v.x * v.x + v.y * v.y;
        }
        sum += __shfl_xor_sync(0xffffffffu, sum, 1);
        sq  += __shfl_xor_sync(0xffffffffu, sq, 1);
        sum += __shfl_xor_sync(0xffffffffu, sum, 2);
        sq  += __shfl_xor_sync(0xffffffffu, sq, 2);
        float mu  = sum * (1.f / 256.f);
        float var = sq * (1.f / 256.f) - mu * mu;
        float rs  = rsqrtf(var + 1e-5f);
#pragma unroll 8
        for (int j = 0; j < 32; ++j) {
            int c = 8 * j + 2 * q;
            float2 v = *(const float2*)(xr + c);
            float xn0 = (v.x - mu) * rs * fsm[c] + fsm[256 + c];
            float xn1 = (v.y - mu) * rs * fsm[c + 1] + fsm[256 + c + 1];
            xa[2 * j]     += xn0;
            xa[2 * j + 1] += xn1;
            smu[P1_XNH + r * 132 + 4 * j + q] = pack_f16(xn0, xn1);
        }
        __syncthreads();

        // ---- mma: 16 rows x 32 cols per warp, k=256, hi+lo B passes ----
        float acc[4][4];
#pragma unroll
        for (int ni = 0; ni < 4; ++ni)
#pragma unroll
            for (int f = 0; f < 4; ++f) acc[ni][f] = 0.f;

#pragma unroll 4
        for (int ks = 0; ks < 16; ++ks) {
            const uint32_t* Ar = smu + P1_XNH + (m0w + gid) * 132 + ks * 8 + tig;
            uint32_t a0 = Ar[0], a1 = Ar[8 * 132], a2 = Ar[4], a3 = Ar[8 * 132 + 4];
#pragma unroll
            for (int p = 0; p < 2; ++p) {
                const uint32_t* Bp = smu + (p ? P1_BL : P1_BH);
#pragma unroll
                for (int ni = 0; ni < 4; ++ni) {
                    const uint32_t* Br = Bp + (n0w + ni * 8 + gid) * 132 + ks * 8 + tig;
                    uint32_t b0 = Br[0], b1 = Br[4];
                    asm volatile(
                        "mma.sync.aligned.m16n8k16.row.col.f32.f16.f16.f32 "
                        "{%0,%1,%2,%3}, {%4,%5,%6,%7}, {%8,%9}, {%0,%1,%2,%3};"
                        : "+f"(acc[ni][0]), "+f"(acc[ni][1]),
                          "+f"(acc[ni][2]), "+f"(acc[ni][3])
                        : "r"(a0), "r"(a1), "r"(a2), "r"(a3), "r"(b0), "r"(b1));
                }
            }
        }

        // ---- store K/V (fp32, transposed [i][t][j]) ----
#pragma unroll
        for (int ni = 0; ni < 4; ++ni) {
            int c = n0w + ni * 8 + tig * 2;
            int r0 = m0w + gid;
            float2 v0 = make_float2(acc[ni][0], acc[ni][1]);
            float2 v1 = make_float2(acc[ni][2], acc[ni][3]);
            *(float2*)(g_KV + ((size_t)(i0 + r0) * Sdim + s) * 64 + c) = v0;
            *(float2*)(g_KV + ((size_t)(i0 + r0 + 8) * Sdim + s) * 64 + c) = v1;
        }
        __syncthreads();
    }

    // ---- Xsum atomics ----
#pragma unroll 4
    for (int j = 0; j < 32; ++j) {
        int c = 8 * j + 2 * q;
        atomicAdd(&g_Xsum[(i0 + r) * 256 + c],     xa[2 * j]);
        atomicAdd(&g_Xsum[(i0 + r) * 256 + c + 1], xa[2 * j + 1]);
    }
}

// ================= pass 2q: Qbar = (Xsum/S) @ Wq (parallel n-tiles) =================
__global__ __launch_bounds__(256, 1)
void pass2q_kernel(const float* __restrict__ Wq) {
    extern __shared__ float sm[];
    float* xbt = sm;            // 8*256
    float* wqs = sm + 2048;     // 256*64

    const int tid = threadIdx.x;
    const int i0 = blockIdx.x * 8, n0 = blockIdx.y * 64;

    for (int idx = tid; idx < 2048; idx += 256)
        xbt[idx] = g_Xsum[i0 * 256 + idx] * (1.f / (float)Sdim);
    for (int idx = tid; idx < 256 * 16; idx += 256) {
        int kk = idx >> 4, c4 = idx & 15;
        ((float4*)(wqs + kk * 64))[c4] = *(const float4*)(Wq + kk * 256 + n0 + c4 * 4);
    }
    __syncthreads();

    const int col = tid & 63, rr = tid >> 6;
    float a0 = 0.f, a1 = 0.f;
#pragma unroll 8
    for (int kk = 0; kk < 256; ++kk) {
        float wv = wqs[kk * 64 + col];
        a0 += xbt[rr * 256 + kk] * wv;
        a1 += xbt[(rr + 4) * 256 + kk] * wv;
    }
    g_Qbar[(i0 + rr) * 256 + n0 + col] = a0;
    g_Qbar[(i0 + rr + 4) * 256 + n0 + col] = a1;
}

// ================= pass 2a: attention per column (coalesced KV) =================
#define KVP 65
__global__ __launch_bounds__(256, 1)
void pass2a_kernel() {
    extern __shared__ float sm[];
    float* qb  = sm;
    float* kvs = sm + 256;
    float* sc  = kvs + 256 * KVP;

    const int i = blockIdx.x, tid = threadIdx.x;
    qb[tid] = g_Qbar[i * 256 + tid];

    const float4* src = (const float4*)(g_KV + (size_t)i * Sdim * 64);
    for (int idx = tid; idx < 256 * 16; idx += 256) {
        int t = idx >> 4, j4 = idx & 15;
        float4 v = src[idx];
        float* d = kvs + t * KVP + j4 * 4;
        d[0] = v.x; d[1] = v.y; d[2] = v.z; d[3] = v.w;
    }
    __syncthreads();

    const int h = tid >> 5, lt = tid & 31;
    float sv[8];
#pragma unroll
    for (int k = 0; k < 8; ++k) {
        int t = lt + 32 * k;
        float s = 0.f;
#pragma unroll
        for (int d = 0; d < 32; ++d) s += qb[h * 32 + d] * kvs[t * KVP + d];
        sv[k] = s * 0.17677669529663687f;
    }
    float mx = sv[0];
#pragma unroll
    for (int k = 1; k < 8; ++k) mx = fmaxf(mx, sv[k]);
#pragma unroll
    for (int off = 16; off > 0; off >>= 1) mx = fmaxf(mx, __shfl_xor_sync(0xffffffffu, mx, off));
    float sum = 0.f;
#pragma unroll
    for (int k = 0; k < 8; ++k) { sv[k] = __expf(sv[k] - mx); sum += sv[k]; }
#pragma unroll
    for (int off = 16; off > 0; off >>= 1) sum += __shfl_xor_sync(0xffffffffu, sum, off);
    float rinv = 1.f / sum;
#pragma unroll
    for (int k = 0; k < 8; ++k) sc[h * 256 + lt + 32 * k] = sv[k] * rinv;
    __syncthreads();

    const int d = tid & 31;
    float wacc = 0.f;
#pragma unroll 4
    for (int t = 0; t < 256; ++t) wacc += sc[h * 256 + t] * kvs[t * KVP + 32 + d];
    g_Wgt[(size_t)i * 256 + h * 32 + d] = wacc;
}

// ================= pass 2b: mma.sync fp16 2-pass (LN + Wg GEMM + gate + Wo GEMM) =================
#define SM_AH 1024
#define SM_B  17920
#define SM2B_BYTES ((17920 + 2 * 9216) * 4)

__device__ __forceinline__ const uint4* chunk_src(int j) {
    int g = j >> 3, jj = j & 7, kc = jj >> 1;
    const uint32_t* base = (jj & 1) ? g_B32lo : g_B32hi;
    return (const uint4*)(base + (g * 4 + kc) * 8192);
}

__device__ __forceinline__ void mma_pass(const uint32_t* __restrict__ A,
                                         const uint32_t* __restrict__ B,
                                         int kc, int m0, int n0, int gid, int tig,
                                         float acc[4][8][4]) {
#pragma unroll
    for (int s = 0; s < 4; ++s) {
        const int kpA = kc * 32 + s * 8 + tig;
        uint32_t a[4][4];
#pragma unroll
        for (int mi = 0; mi < 4; ++mi) {
            const uint32_t* Ar = A + (m0 + mi * 16 + gid) * APITCH + kpA;
            a[mi][0] = Ar[0];
            a[mi][1] = Ar[8 * APITCH];
            a[mi][2] = Ar[4];
            a[mi][3] = Ar[8 * APITCH + 4];
        }
#pragma unroll
        for (int ni = 0; ni < 8; ++ni) {
            const uint32_t* Br = B + (n0 + ni * 8 + gid) * BPITCH + s * 8 + tig;
            uint32_t b0 = Br[0], b1 = Br[4];
#pragma unroll
            for (int mi = 0; mi < 4; ++mi) {
                asm volatile(
                    "mma.sync.aligned.m16n8k16.row.col.f32.f16.f16.f32 "
                    "{%0,%1,%2,%3}, {%4,%5,%6,%7}, {%8,%9}, {%0,%1,%2,%3};"
                    : "+f"(acc[mi][ni][0]), "+f"(acc[mi][ni][1]),
                      "+f"(acc[mi][ni][2]), "+f"(acc[mi][ni][3])
                    : "r"(a[mi][0]), "r"(a[mi][1]), "r"(a[mi][2]), "r"(a[mi][3]),
                      "r"(b0), "r"(b1));
            }
        }
    }
}

__global__ __launch_bounds__(256, 1)
void pass2b_mma_kernel(const float* __restrict__ x, const float* __restrict__ gamma,
                       const float* __restrict__ beta, const float* __restrict__ bg,
                       const float* __restrict__ bo, float* __restrict__ out) {
    extern __shared__ uint32_t smu[];
    float* fsm = (float*)smu;
    const int tid = threadIdx.x;
    const int wid = tid >> 5, lane = tid & 31;
    const int gid = lane >> 2, tig = lane & 3;
    const int m0 = (wid >> 2) * 64, n0 = (wid & 3) * 64;
    const size_t r0 = (size_t)blockIdx.x * 128;
    const int i0 = (int)(r0 % Idim);

    fsm[tid] = gamma[tid];
    fsm[256 + tid] = beta[tid];
    fsm[512 + tid] = bg[tid];
    fsm[768 + tid] = bo[tid];
    __syncthreads();

    // ---- LN: two threads per row; normalize + pack fp16 ----
    {
        const int r = tid >> 1, cb = (tid & 1) * 128;
        const float* xr = x + (r0 + r) * Cdim + cb;
        float sum = 0.f, sq = 0.f;
#pragma unroll 8
        for (int c = 0; c < 128; c += 4) {
            float4 v = *(const float4*)(xr + c);
            sum += v.x + v.y + v.z + v.w;
            sq  += v.x * v.x + v.y * v.y + v.z * v.z + v.w * v.w;
        }
        sum += __shfl_xor_sync(0xffffffffu, sum, 1);
        sq  += __shfl_xor_sync(0xffffffffu, sq, 1);
        float mu  = sum * (1.f / 256.f);
        float var = sq * (1.f / 256.f) - mu * mu;
        float rs  = rsqrtf(var + 1e-5f);
        uint32_t* Ah = smu + SM_AH + r * APITCH + (cb >> 1);
#pragma unroll 4
        for (int j4 = 0; j4 < 32; ++j4) {
            float4 v = *(const float4*)(xr + j4 * 4);
            int c = cb + j4 * 4;
            float x0 = (v.x - mu) * rs * fsm[c + 0] + fsm[256 + c + 0];
            float x1 = (v.y - mu) * rs * fsm[c + 1] + fsm[256 + c + 1];
            float x2 = (v.z - mu) * rs * fsm[c + 2] + fsm[256 + c + 2];
            float x3 = (v.w - mu) * rs * fsm[c + 3] + fsm[256 + c + 3];
            Ah[j4 * 2 + 0] = pack_f16(x0, x1);
            Ah[j4 * 2 + 1] = pack_f16(x2, x3);
        }
    }

    // ---- stage chunk 0 ----
    {
        const uint4* s = chunk_src(0);
        uint4* d = (uint4*)(smu + SM_B);
#pragma unroll
        for (int t = 0; t < 8; ++t) {
            int u = tid + t * 256;
            int n = u >> 3, kq = u & 7;
            d[n * 9 + kq] = s[u];
        }
    }
    __syncthreads();

    float acc[4][8][4] = {};
    int cur = 0;

    for (int j = 0; j < 16; ++j) {
        uint4 pf[8];
        if (j < 15) {
            const uint4* s = chunk_src(j + 1);
#pragma unroll
            for (int t = 0; t < 8; ++t) pf[t] = s[tid + t * 256];
        }
        const int kc = (j & 7) >> 1;
        const uint32_t* Bb = smu + SM_B + cur * 9216;
        mma_pass(smu + SM_AH, Bb, kc, m0, n0, gid, tig, acc);
        if (j < 15) {
            uint4* d = (uint4*)(smu + SM_B + (cur ^ 1) * 9216);
#pragma unroll
            for (int t = 0; t < 8; ++t) {
                int u = tid + t * 256;
                int n = u >> 3, kq = u & 7;
                d[n * 9 + kq] = pf[t];
            }
        }
        __syncthreads();
        cur ^= 1;

        if (j == 7) {
            // ---- epilogue 1: val = sigmoid(acc + bg) * wgt -> A (fp16) ----
#pragma unroll
            for (int mi = 0; mi < 4; ++mi) {
#pragma unroll
                for (int ni = 0; ni < 8; ++ni) {
                    int c = n0 + ni * 8 + tig * 2;
#pragma unroll
                    for (int half = 0; half < 2; ++half) {
                        int r = m0 + mi * 16 + gid + half * 8;
                        float2 w = *(const float2*)(g_Wgt + (size_t)(i0 + r) * 256 + c);
                        float t0 = acc[mi][ni][half * 2 + 0] + fsm[512 + c];
                        float t1 = acc[mi][ni][half * 2 + 1] + fsm[512 + c + 1];
                        float v0 = w.x / (1.f + __expf(-t0));
                        float v1 = w.y / (1.f + __expf(-t1));
                        smu[SM_AH + r * APITCH + (c >> 1)] = pack_f16(v0, v1);
                        acc[mi][ni][half * 2 + 0] = 0.f;
                        acc[mi][ni][half * 2 + 1] = 0.f;
                    }
                }
            }
            __syncthreads();
        }
    }

    // ---- epilogue 2: out = acc + bo ----
#pragma unroll
    for (int mi = 0; mi < 4; ++mi) {
#pragma unroll
        for (int ni = 0; ni < 8; ++ni) {
            int c = n0 + ni * 8 + tig * 2;
#pragma unroll
            for (int half = 0; half < 2; ++half) {
                int r = m0 + mi * 16 + gid + half * 8;
                float2 v;
                v.x = acc[mi][ni][half * 2 + 0] + fsm[768 + c];
                v.y = acc[mi][ni][half * 2 + 1] + fsm[768 + c + 1];
                *(float2*)(out + (r0 + r) * Cdim + c) = v;
            }
        }
    }
}

// ---------------- launch ----------------
extern "C" void kernel_launch(void* const* d_in, const int* in_sizes, int n_in,
                              void* d_out, int out_size) {
    const float* x     = (const float*)d_in[0];
    const float* gamma = (const float*)d_in[1];
    const float* beta  = (const float*)d_in[2];
    const float* Wq    = (const float*)d_in[3];
    const float* Wk    = (const float*)d_in[4];
    const float* Wv    = (const float*)d_in[5];
    const float* Wg    = (const float*)d_in[6];
    const float* bg    = (const float*)d_in[7];
    const float* Wo    = (const float*)d_in[8];
    const float* bo    = (const float*)d_in[9];
    float* out = (float*)d_out;

    const int SMEM1  = P1_SMEM_U32 * 4;
    const int SMEM2Q = (2048 + 256 * 64) * 4;
    const int SMEM2A = (256 + 256 * KVP + 8 * 256) * 4;

    cudaFuncSetAttribute(pass1_kernel,      cudaFuncAttributeMaxDynamicSharedMemorySize, SMEM1);
    cudaFuncSetAttribute(pass2q_kernel,     cudaFuncAttributeMaxDynamicSharedMemorySize, SMEM2Q);
    cudaFuncSetAttribute(pass2a_kernel,     cudaFuncAttributeMaxDynamicSharedMemorySize, SMEM2A);
    cudaFuncSetAttribute(pass2b_mma_kernel, cudaFuncAttributeMaxDynamicSharedMemorySize, SM2B_BYTES);

    prep_weights_kernel<<<256, 256>>>(Wg, Wo);
    prep_kv_kernel<<<32, 256>>>(Wk, Wv);
    pass1_kernel<<<dim3(Idim / 64, Sdim / 8), 256, SMEM1>>>(x, gamma, beta);
    pass2q_kernel<<<dim3(64, 4), 256, SMEM2Q>>>(Wq);
    pass2a_kernel<<<Idim, 256, SMEM2A>>>();
    pass2b_mma_kernel<<<SI / 128, 256, SM2B_BYTES>>>(x, gamma, beta, bg, bo, out);
}

// round 12
// speedup vs baseline: 1.6251x; 1.1759x over previous
#include <cuda_runtime.h>
#include <cuda_bf16.h>
#include <cuda_fp16.h>
#include <cstdint>
#include <math.h>

#define Sdim 256
#define Idim 512
#define Cdim 256
#define HD   256
#define SI   (Sdim*Idim)
#define APITCH 132
#define BPITCH 36

// ---------------- device scratch ----------------
__device__ float g_KV[(size_t)SI * 64];     // transposed: [i][t][j]  (i*Sdim+t)*64+j
__device__ float g_Xsum[Idim * Cdim];
__device__ float g_Qbar[Idim * HD];
__device__ float g_Wgt[Idim * HD];
// chunk-major packed fp16-pair weights (hi only): [(g*4+kc)*8192 + n*32 + kp]
__device__ uint32_t g_B32hi[2 * 4 * 8192];
// Wkv fp16 pairs: [n (0..63)][kp (0..127)]
__device__ uint32_t g_KVW32hi[64 * 128];
__device__ uint32_t g_KVW32lo[64 * 128];

__device__ __forceinline__ uint32_t pack_f16(float a, float b) {
    __half2 t = __floats2half2_rn(a, b);
    return *(uint32_t*)&t;
}

// ---------------- prep: Wg/Wo fp16 pack + Xsum zero ----------------
__global__ void prep_weights_kernel(const float* __restrict__ Wg, const float* __restrict__ Wo) {
    int d = blockIdx.x * blockDim.x + threadIdx.x;
    if (d >= 65536) return;
    g_Xsum[d] = 0.f;
    g_Xsum[d + 65536] = 0.f;
    int n  = d & 255;
    int kp = (d >> 8) & 31;
    int kc = (d >> 13) & 3;
    int g  = d >> 15;
    const float* W = g ? Wo : Wg;
    int k0 = kc * 64 + kp * 2;
    float w0 = W[k0 * 256 + n], w1 = W[(k0 + 1) * 256 + n];
    int idx = (g * 4 + kc) * 8192 + n * 32 + kp;
    g_B32hi[idx] = pack_f16(w0, w1);
}

// ---------------- prep: Wk|Wv fp16 split, [n][kp] pair-major ----------------
__global__ void prep_kv_kernel(const float* __restrict__ Wk, const float* __restrict__ Wv) {
    int d = blockIdx.x * blockDim.x + threadIdx.x;
    if (d >= 64 * 128) return;
    int n = d >> 7, kp = d & 127;
    int k0 = kp * 2;
    float w0 = (n < 32) ? Wk[k0 * 32 + n] : Wv[k0 * 32 + (n - 32)];
    float w1 = (n < 32) ? Wk[(k0 + 1) * 32 + n] : Wv[(k0 + 1) * 32 + (n - 32)];
    __half h0 = __float2half_rn(w0), h1 = __float2half_rn(w1);
    g_KVW32hi[d] = pack_f16(__half2float(h0), __half2float(h1));
    g_KVW32lo[d] = pack_f16(w0 - __half2float(h0), w1 - __half2float(h1));
}

// ================= pass 1: LN + K/V proj via mma + xn column-sum =================
#define P1_XNH 512
#define P1_BH  (512 + 64 * 132)
#define P1_BL  (P1_BH + 64 * 132)
#define P1_SMEM_U32 (P1_BL + 64 * 132)

__global__ __launch_bounds__(256, 1)
void pass1_kernel(const float* __restrict__ x, const float* __restrict__ gamma,
                  const float* __restrict__ beta) {
    extern __shared__ uint32_t smu[];
    float* fsm = (float*)smu;
    const int tid = threadIdx.x;
    const int wid = tid >> 5, lane = tid & 31;
    const int gid = lane >> 2, tig = lane & 3;
    const int mw = wid >> 1, nw = wid & 1;        // warp tile: 16 rows x 32 cols
    const int m0w = mw * 16, n0w = nw * 32;
    const int i0 = blockIdx.x * 64, s0 = blockIdx.y * 8;
    const int r = tid >> 2, q = tid & 3;          // LN: 4 threads per row

    fsm[tid] = gamma[tid];
    fsm[256 + tid] = beta[tid];
    for (int idx = tid; idx < 8192; idx += 256) {
        int n = idx >> 7, kp = idx & 127;
        smu[P1_BH + n * 132 + kp] = g_KVW32hi[idx];
        smu[P1_BL + n * 132 + kp] = g_KVW32lo[idx];
    }

    float xa[64];
#pragma unroll
    for (int j = 0; j < 64; ++j) xa[j] = 0.f;
    __syncthreads();

    for (int ss = 0; ss < 8; ++ss) {
        const int s = s0 + ss;
        const float* xr = x + ((size_t)(s * Idim + i0 + r)) * Cdim;

        float sum = 0.f, sq = 0.f;
#pragma unroll 8
        for (int j = 0; j < 32; ++j) {
            float2 v = *(const float2*)(xr + 8 * j + 2 * q);
            sum += v.x + v.y;
            sq  += v.x * v.x + v.y * v.y;
        }
        sum += __shfl_xor_sync(0xffffffffu, sum, 1);
        sq  += __shfl_xor_sync(0xffffffffu, sq, 1);
        sum += __shfl_xor_sync(0xffffffffu, sum, 2);
        sq  += __shfl_xor_sync(0xffffffffu, sq, 2);
        float mu  = sum * (1.f / 256.f);
        float var = sq * (1.f / 256.f) - mu * mu;
        float rs  = rsqrtf(var + 1e-5f);
#pragma unroll 8
        for (int j = 0; j < 32; ++j) {
            int c = 8 * j + 2 * q;
            float2 v = *(const float2*)(xr + c);
            float xn0 = (v.x - mu) * rs * fsm[c] + fsm[256 + c];
            float xn1 = (v.y - mu) * rs * fsm[c + 1] + fsm[256 + c + 1];
            xa[2 * j]     += xn0;
            xa[2 * j + 1] += xn1;
            smu[P1_XNH + r * 132 + 4 * j + q] = pack_f16(xn0, xn1);
        }
        __syncthreads();

        float acc[4][4];
#pragma unroll
        for (int ni = 0; ni < 4; ++ni)
#pragma unroll
            for (int f = 0; f < 4; ++f) acc[ni][f] = 0.f;

#pragma unroll 4
        for (int ks = 0; ks < 16; ++ks) {
            const uint32_t* Ar = smu + P1_XNH + (m0w + gid) * 132 + ks * 8 + tig;
            uint32_t a0 = Ar[0], a1 = Ar[8 * 132], a2 = Ar[4], a3 = Ar[8 * 132 + 4];
#pragma unroll
            for (int p = 0; p < 2; ++p) {
                const uint32_t* Bp = smu + (p ? P1_BL : P1_BH);
#pragma unroll
                for (int ni = 0; ni < 4; ++ni) {
                    const uint32_t* Br = Bp + (n0w + ni * 8 + gid) * 132 + ks * 8 + tig;
                    uint32_t b0 = Br[0], b1 = Br[4];
                    asm volatile(
                        "mma.sync.aligned.m16n8k16.row.col.f32.f16.f16.f32 "
                        "{%0,%1,%2,%3}, {%4,%5,%6,%7}, {%8,%9}, {%0,%1,%2,%3};"
                        : "+f"(acc[ni][0]), "+f"(acc[ni][1]),
                          "+f"(acc[ni][2]), "+f"(acc[ni][3])
                        : "r"(a0), "r"(a1), "r"(a2), "r"(a3), "r"(b0), "r"(b1));
                }
            }
        }

#pragma unroll
        for (int ni = 0; ni < 4; ++ni) {
            int c = n0w + ni * 8 + tig * 2;
            int r0 = m0w + gid;
            float2 v0 = make_float2(acc[ni][0], acc[ni][1]);
            float2 v1 = make_float2(acc[ni][2], acc[ni][3]);
            *(float2*)(g_KV + ((size_t)(i0 + r0) * Sdim + s) * 64 + c) = v0;
            *(float2*)(g_KV + ((size_t)(i0 + r0 + 8) * Sdim + s) * 64 + c) = v1;
        }
        __syncthreads();
    }

#pragma unroll 4
    for (int j = 0; j < 32; ++j) {
        int c = 8 * j + 2 * q;
        atomicAdd(&g_Xsum[(i0 + r) * 256 + c],     xa[2 * j]);
        atomicAdd(&g_Xsum[(i0 + r) * 256 + c + 1], xa[2 * j + 1]);
    }
}

// ================= pass 2q: Qbar = (Xsum/S) @ Wq (parallel n-tiles) =================
__global__ __launch_bounds__(256, 1)
void pass2q_kernel(const float* __restrict__ Wq) {
    extern __shared__ float sm[];
    float* xbt = sm;            // 8*256
    float* wqs = sm + 2048;     // 256*64

    const int tid = threadIdx.x;
    const int i0 = blockIdx.x * 8, n0 = blockIdx.y * 64;

    for (int idx = tid; idx < 2048; idx += 256)
        xbt[idx] = g_Xsum[i0 * 256 + idx] * (1.f / (float)Sdim);
    for (int idx = tid; idx < 256 * 16; idx += 256) {
        int kk = idx >> 4, c4 = idx & 15;
        ((float4*)(wqs + kk * 64))[c4] = *(const float4*)(Wq + kk * 256 + n0 + c4 * 4);
    }
    __syncthreads();

    const int col = tid & 63, rr = tid >> 6;
    float a0 = 0.f, a1 = 0.f;
#pragma unroll 8
    for (int kk = 0; kk < 256; ++kk) {
        float wv = wqs[kk * 64 + col];
        a0 += xbt[rr * 256 + kk] * wv;
        a1 += xbt[(rr + 4) * 256 + kk] * wv;
    }
    g_Qbar[(i0 + rr) * 256 + n0 + col] = a0;
    g_Qbar[(i0 + rr + 4) * 256 + n0 + col] = a1;
}

// ================= pass 2a: attention per column (coalesced KV) =================
#define KVP 65
__global__ __launch_bounds__(256, 1)
void pass2a_kernel() {
    extern __shared__ float sm[];
    float* qb  = sm;
    float* kvs = sm + 256;
    float* sc  = kvs + 256 * KVP;

    const int i = blockIdx.x, tid = threadIdx.x;
    qb[tid] = g_Qbar[i * 256 + tid];

    const float4* src = (const float4*)(g_KV + (size_t)i * Sdim * 64);
    for (int idx = tid; idx < 256 * 16; idx += 256) {
        int t = idx >> 4, j4 = idx & 15;
        float4 v = src[idx];
        float* d = kvs + t * KVP + j4 * 4;
        d[0] = v.x; d[1] = v.y; d[2] = v.z; d[3] = v.w;
    }
    __syncthreads();

    const int h = tid >> 5, lt = tid & 31;
    float sv[8];
#pragma unroll
    for (int k = 0; k < 8; ++k) {
        int t = lt + 32 * k;
        float s = 0.f;
#pragma unroll
        for (int d = 0; d < 32; ++d) s += qb[h * 32 + d] * kvs[t * KVP + d];
        sv[k] = s * 0.17677669529663687f;
    }
    float mx = sv[0];
#pragma unroll
    for (int k = 1; k < 8; ++k) mx = fmaxf(mx, sv[k]);
#pragma unroll
    for (int off = 16; off > 0; off >>= 1) mx = fmaxf(mx, __shfl_xor_sync(0xffffffffu, mx, off));
    float sum = 0.f;
#pragma unroll
    for (int k = 0; k < 8; ++k) { sv[k] = __expf(sv[k] - mx); sum += sv[k]; }
#pragma unroll
    for (int off = 16; off > 0; off >>= 1) sum += __shfl_xor_sync(0xffffffffu, sum, off);
    float rinv = 1.f / sum;
#pragma unroll
    for (int k = 0; k < 8; ++k) sc[h * 256 + lt + 32 * k] = sv[k] * rinv;
    __syncthreads();

    const int d = tid & 31;
    float wacc = 0.f;
#pragma unroll 4
    for (int t = 0; t < 256; ++t) wacc += sc[h * 256 + t] * kvs[t * KVP + 32 + d];
    g_Wgt[(size_t)i * 256 + h * 32 + d] = wacc;
}

// ================= pass 2b: mma.sync fp16 (LN + Wg GEMM + gate + Wo GEMM), hi-only B =================
#define SM_AH 1024
#define SM_B  17920
#define SM2B_BYTES ((17920 + 2 * 9216) * 4)

__device__ __forceinline__ const uint4* chunk_src(int j) {
    int g = j >> 2, kc = j & 3;
    return (const uint4*)(g_B32hi + (g * 4 + kc) * 8192);
}

__device__ __forceinline__ void mma_pass(const uint32_t* __restrict__ A,
                                         const uint32_t* __restrict__ B,
                                         int kc, int m0, int n0, int gid, int tig,
                                         float acc[4][8][4]) {
#pragma unroll
    for (int s = 0; s < 4; ++s) {
        const int kpA = kc * 32 + s * 8 + tig;
        uint32_t a[4][4];
#pragma unroll
        for (int mi = 0; mi < 4; ++mi) {
            const uint32_t* Ar = A + (m0 + mi * 16 + gid) * APITCH + kpA;
            a[mi][0] = Ar[0];
            a[mi][1] = Ar[8 * APITCH];
            a[mi][2] = Ar[4];
            a[mi][3] = Ar[8 * APITCH + 4];
        }
#pragma unroll
        for (int ni = 0; ni < 8; ++ni) {
            const uint32_t* Br = B + (n0 + ni * 8 + gid) * BPITCH + s * 8 + tig;
            uint32_t b0 = Br[0], b1 = Br[4];
#pragma unroll
            for (int mi = 0; mi < 4; ++mi) {
                asm volatile(
                    "mma.sync.aligned.m16n8k16.row.col.f32.f16.f16.f32 "
                    "{%0,%1,%2,%3}, {%4,%5,%6,%7}, {%8,%9}, {%0,%1,%2,%3};"
                    : "+f"(acc[mi][ni][0]), "+f"(acc[mi][ni][1]),
                      "+f"(acc[mi][ni][2]), "+f"(acc[mi][ni][3])
                    : "r"(a[mi][0]), "r"(a[mi][1]), "r"(a[mi][2]), "r"(a[mi][3]),
                      "r"(b0), "r"(b1));
            }
        }
    }
}

__global__ __launch_bounds__(256, 1)
void pass2b_mma_kernel(const float* __restrict__ x, const float* __restrict__ gamma,
                       const float* __restrict__ beta, const float* __restrict__ bg,
                       const float* __restrict__ bo, float* __restrict__ out) {
    extern __shared__ uint32_t smu[];
    float* fsm = (float*)smu;
    const int tid = threadIdx.x;
    const int wid = tid >> 5, lane = tid & 31;
    const int gid = lane >> 2, tig = lane & 3;
    const int m0 = (wid >> 2) * 64, n0 = (wid & 3) * 64;
    const size_t r0 = (size_t)blockIdx.x * 128;
    const int i0 = (int)(r0 % Idim);

    fsm[tid] = gamma[tid];
    fsm[256 + tid] = beta[tid];
    fsm[512 + tid] = bg[tid];
    fsm[768 + tid] = bo[tid];
    __syncthreads();

    // ---- LN: two threads per row; normalize + pack fp16 ----
    {
        const int r = tid >> 1, cb = (tid & 1) * 128;
        const float* xr = x + (r0 + r) * Cdim + cb;
        float sum = 0.f, sq = 0.f;
#pragma unroll 8
        for (int c = 0; c < 128; c += 4) {
            float4 v = *(const float4*)(xr + c);
            sum += v.x + v.y + v.z + v.w;
            sq  += v.x * v.x + v.y * v.y + v.z * v.z + v.w * v.w;
        }
        sum += __shfl_xor_sync(0xffffffffu, sum, 1);
        sq  += __shfl_xor_sync(0xffffffffu, sq, 1);
        float mu  = sum * (1.f / 256.f);
        float var = sq * (1.f / 256.f) - mu * mu;
        float rs  = rsqrtf(var + 1e-5f);
        uint32_t* Ah = smu + SM_AH + r * APITCH + (cb >> 1);
#pragma unroll 4
        for (int j4 = 0; j4 < 32; ++j4) {
            float4 v = *(const float4*)(xr + j4 * 4);
            int c = cb + j4 * 4;
            float x0 = (v.x - mu) * rs * fsm[c + 0] + fsm[256 + c + 0];
            float x1 = (v.y - mu) * rs * fsm[c + 1] + fsm[256 + c + 1];
            float x2 = (v.z - mu) * rs * fsm[c + 2] + fsm[256 + c + 2];
            float x3 = (v.w - mu) * rs * fsm[c + 3] + fsm[256 + c + 3];
            Ah[j4 * 2 + 0] = pack_f16(x0, x1);
            Ah[j4 * 2 + 1] = pack_f16(x2, x3);
        }
    }

    // ---- stage chunk 0 ----
    {
        const uint4* s = chunk_src(0);
        uint4* d = (uint4*)(smu + SM_B);
#pragma unroll
        for (int t = 0; t < 8; ++t) {
            int u = tid + t * 256;
            int n = u >> 3, kq = u & 7;
            d[n * 9 + kq] = s[u];
        }
    }
    __syncthreads();

    float acc[4][8][4] = {};
    int cur = 0;

    for (int j = 0; j < 8; ++j) {
        uint4 pf[8];
        if (j < 7) {
            const uint4* s = chunk_src(j + 1);
#pragma unroll
            for (int t = 0; t < 8; ++t) pf[t] = s[tid + t * 256];
        }
        const int kc = j & 3;
        const uint32_t* Bb = smu + SM_B + cur * 9216;
        mma_pass(smu + SM_AH, Bb, kc, m0, n0, gid, tig, acc);
        if (j < 7) {
            uint4* d = (uint4*)(smu + SM_B + (cur ^ 1) * 9216);
#pragma unroll
            for (int t = 0; t < 8; ++t) {
                int u = tid + t * 256;
                int n = u >> 3, kq = u & 7;
                d[n * 9 + kq] = pf[t];
            }
        }
        __syncthreads();
        cur ^= 1;

        if (j == 3) {
            // ---- epilogue 1: val = sigmoid(acc + bg) * wgt -> A (fp16) ----
#pragma unroll
            for (int mi = 0; mi < 4; ++mi) {
#pragma unroll
                for (int ni = 0; ni < 8; ++ni) {
                    int c = n0 + ni * 8 + tig * 2;
#pragma unroll
                    for (int half = 0; half < 2; ++half) {
                        int r = m0 + mi * 16 + gid + half * 8;
                        float2 w = *(const float2*)(g_Wgt + (size_t)(i0 + r) * 256 + c);
                        float t0 = acc[mi][ni][half * 2 + 0] + fsm[512 + c];
                        float t1 = acc[mi][ni][half * 2 + 1] + fsm[512 + c + 1];
                        float v0 = w.x / (1.f + __expf(-t0));
                        float v1 = w.y / (1.f + __expf(-t1));
                        smu[SM_AH + r * APITCH + (c >> 1)] = pack_f16(v0, v1);
                        acc[mi][ni][half * 2 + 0] = 0.f;
                        acc[mi][ni][half * 2 + 1] = 0.f;
                    }
                }
            }
            __syncthreads();
        }
    }

    // ---- epilogue 2: out = acc + bo ----
#pragma unroll
    for (int mi = 0; mi < 4; ++mi) {
#pragma unroll
        for (int ni = 0; ni < 8; ++ni) {
            int c = n0 + ni * 8 + tig * 2;
#pragma unroll
            for (int half = 0; half < 2; ++half) {
                int r = m0 + mi * 16 + gid + half * 8;
                float2 v;
                v.x = acc[mi][ni][half * 2 + 0] + fsm[768 + c];
                v.y = acc[mi][ni][half * 2 + 1] + fsm[768 + c + 1];
                *(float2*)(out + (r0 + r) * Cdim + c) = v;
            }
        }
    }
}

// ---------------- launch ----------------
extern "C" void kernel_launch(void* const* d_in, const int* in_sizes, int n_in,
                              void* d_out, int out_size) {
    const float* x     = (const float*)d_in[0];
    const float* gamma = (const float*)d_in[1];
    const float* beta  = (const float*)d_in[2];
    const float* Wq    = (const float*)d_in[3];
    const float* Wk    = (const float*)d_in[4];
    const float* Wv    = (const float*)d_in[5];
    const float* Wg    = (const float*)d_in[6];
    const float* bg    = (const float*)d_in[7];
    const float* Wo    = (const float*)d_in[8];
    const float* bo    = (const float*)d_in[9];
    float* out = (float*)d_out;

    const int SMEM1  = P1_SMEM_U32 * 4;
    const int SMEM2Q = (2048 + 256 * 64) * 4;
    const int SMEM2A = (256 + 256 * KVP + 8 * 256) * 4;

    cudaFuncSetAttribute(pass1_kernel,      cudaFuncAttributeMaxDynamicSharedMemorySize, SMEM1);
    cudaFuncSetAttribute(pass2q_kernel,     cudaFuncAttributeMaxDynamicSharedMemorySize, SMEM2Q);
    cudaFuncSetAttribute(pass2a_kernel,     cudaFuncAttributeMaxDynamicSharedMemorySize, SMEM2A);
    cudaFuncSetAttribute(pass2b_mma_kernel, cudaFuncAttributeMaxDynamicSharedMemorySize, SM2B_BYTES);

    prep_weights_kernel<<<256, 256>>>(Wg, Wo);
    prep_kv_kernel<<<32, 256>>>(Wk, Wv);
    pass1_kernel<<<dim3(Idim / 64, Sdim / 8), 256, SMEM1>>>(x, gamma, beta);
    pass2q_kernel<<<dim3(64, 4), 256, SMEM2Q>>>(Wq);
    pass2a_kernel<<<Idim, 256, SMEM2A>>>();
    pass2b_mma_kernel<<<SI / 128, 256, SM2B_BYTES>>>(x, gamma, beta, bg, bo, out);
}

// round 13
// speedup vs baseline: 1.7958x; 1.1050x over previous
#include <cuda_runtime.h>
#include <cuda_bf16.h>
#include <cuda_fp16.h>
#include <cstdint>
#include <math.h>

#define Sdim 256
#define Idim 512
#define Cdim 256
#define HD   256
#define SI   (Sdim*Idim)
#define APITCH 132
#define BPITCH 36

// ---------------- device scratch ----------------
__device__ float g_KV[(size_t)SI * 64];     // transposed: [i][t][j]  (i*Sdim+t)*64+j
__device__ float g_Xsum[Idim * Cdim];
__device__ float g_Qbar[Idim * HD];
__device__ float g_Wgt[Idim * HD];
__device__ uint32_t g_Xn[(size_t)SI * 128]; // LN(x) as fp16 pairs, row-major
// chunk-major packed fp16-pair weights (hi only): [(g*4+kc)*8192 + n*32 + kp]
__device__ uint32_t g_B32hi[2 * 4 * 8192];
// Wkv fp16 pairs: [n (0..63)][kp (0..127)]
__device__ uint32_t g_KVW32hi[64 * 128];

__device__ __forceinline__ uint32_t pack_f16(float a, float b) {
    __half2 t = __floats2half2_rn(a, b);
    return *(uint32_t*)&t;
}

// ---------------- prep: Wg/Wo fp16 pack + Xsum zero ----------------
__global__ void prep_weights_kernel(const float* __restrict__ Wg, const float* __restrict__ Wo) {
    int d = blockIdx.x * blockDim.x + threadIdx.x;
    if (d >= 65536) return;
    g_Xsum[d] = 0.f;
    g_Xsum[d + 65536] = 0.f;
    int n  = d & 255;
    int kp = (d >> 8) & 31;
    int kc = (d >> 13) & 3;
    int g  = d >> 15;
    const float* W = g ? Wo : Wg;
    int k0 = kc * 64 + kp * 2;
    float w0 = W[k0 * 256 + n], w1 = W[(k0 + 1) * 256 + n];
    int idx = (g * 4 + kc) * 8192 + n * 32 + kp;
    g_B32hi[idx] = pack_f16(w0, w1);
}

// ---------------- prep: Wk|Wv fp16 pack, [n][kp] pair-major ----------------
__global__ void prep_kv_kernel(const float* __restrict__ Wk, const float* __restrict__ Wv) {
    int d = blockIdx.x * blockDim.x + threadIdx.x;
    if (d >= 64 * 128) return;
    int n = d >> 7, kp = d & 127;
    int k0 = kp * 2;
    float w0 = (n < 32) ? Wk[k0 * 32 + n] : Wv[k0 * 32 + (n - 32)];
    float w1 = (n < 32) ? Wk[(k0 + 1) * 32 + n] : Wv[(k0 + 1) * 32 + (n - 32)];
    g_KVW32hi[d] = pack_f16(w0, w1);
}

// ================= pass 1: LN + K/V proj via mma + xn column-sum + g_Xn write =================
#define P1_XNH 512
#define P1_BH  (512 + 64 * 132)
#define P1_SMEM_U32 (P1_BH + 64 * 132)

__global__ __launch_bounds__(256)
void pass1_kernel(const float* __restrict__ x, const float* __restrict__ gamma,
                  const float* __restrict__ beta) {
    extern __shared__ uint32_t smu[];
    float* fsm = (float*)smu;
    const int tid = threadIdx.x;
    const int wid = tid >> 5, lane = tid & 31;
    const int gid = lane >> 2, tig = lane & 3;
    const int mw = wid >> 1, nw = wid & 1;        // warp tile: 16 rows x 32 cols
    const int m0w = mw * 16, n0w = nw * 32;
    const int i0 = blockIdx.x * 64, s0 = blockIdx.y * 8;
    const int r = tid >> 2, q = tid & 3;          // LN: 4 threads per row

    fsm[tid] = gamma[tid];
    fsm[256 + tid] = beta[tid];
    for (int idx = tid; idx < 8192; idx += 256) {
        int n = idx >> 7, kp = idx & 127;
        smu[P1_BH + n * 132 + kp] = g_KVW32hi[idx];
    }

    float xa[64];
#pragma unroll
    for (int j = 0; j < 64; ++j) xa[j] = 0.f;
    __syncthreads();

    for (int ss = 0; ss < 8; ++ss) {
        const int s = s0 + ss;
        const size_t grow = (size_t)(s * Idim + i0 + r);
        const float* xr = x + grow * Cdim;
        uint32_t* xnout = g_Xn + grow * 128;

        float sum = 0.f, sq = 0.f;
#pragma unroll 8
        for (int j = 0; j < 32; ++j) {
            float2 v = *(const float2*)(xr + 8 * j + 2 * q);
            sum += v.x + v.y;
            sq  += v.x * v.x + v.y * v.y;
        }
        sum += __shfl_xor_sync(0xffffffffu, sum, 1);
        sq  += __shfl_xor_sync(0xffffffffu, sq, 1);
        sum += __shfl_xor_sync(0xffffffffu, sum, 2);
        sq  += __shfl_xor_sync(0xffffffffu, sq, 2);
        float mu  = sum * (1.f / 256.f);
        float var = sq * (1.f / 256.f) - mu * mu;
        float rs  = rsqrtf(var + 1e-5f);
#pragma unroll 8
        for (int j = 0; j < 32; ++j) {
            int c = 8 * j + 2 * q;
            float2 v = *(const float2*)(xr + c);
            float xn0 = (v.x - mu) * rs * fsm[c] + fsm[256 + c];
            float xn1 = (v.y - mu) * rs * fsm[c + 1] + fsm[256 + c + 1];
            xa[2 * j]     += xn0;
            xa[2 * j + 1] += xn1;
            uint32_t pk = pack_f16(xn0, xn1);
            smu[P1_XNH + r * 132 + 4 * j + q] = pk;
            xnout[4 * j + q] = pk;
        }
        __syncthreads();

        float acc[4][4];
#pragma unroll
        for (int ni = 0; ni < 4; ++ni)
#pragma unroll
            for (int f = 0; f < 4; ++f) acc[ni][f] = 0.f;

#pragma unroll 4
        for (int ks = 0; ks < 16; ++ks) {
            const uint32_t* Ar = smu + P1_XNH + (m0w + gid) * 132 + ks * 8 + tig;
            uint32_t a0 = Ar[0], a1 = Ar[8 * 132], a2 = Ar[4], a3 = Ar[8 * 132 + 4];
#pragma unroll
            for (int ni = 0; ni < 4; ++ni) {
                const uint32_t* Br = smu + P1_BH + (n0w + ni * 8 + gid) * 132 + ks * 8 + tig;
                uint32_t b0 = Br[0], b1 = Br[4];
                asm volatile(
                    "mma.sync.aligned.m16n8k16.row.col.f32.f16.f16.f32 "
                    "{%0,%1,%2,%3}, {%4,%5,%6,%7}, {%8,%9}, {%0,%1,%2,%3};"
                    : "+f"(acc[ni][0]), "+f"(acc[ni][1]),
                      "+f"(acc[ni][2]), "+f"(acc[ni][3])
                    : "r"(a0), "r"(a1), "r"(a2), "r"(a3), "r"(b0), "r"(b1));
            }
        }

#pragma unroll
        for (int ni = 0; ni < 4; ++ni) {
            int c = n0w + ni * 8 + tig * 2;
            int r0 = m0w + gid;
            float2 v0 = make_float2(acc[ni][0], acc[ni][1]);
            float2 v1 = make_float2(acc[ni][2], acc[ni][3]);
            *(float2*)(g_KV + ((size_t)(i0 + r0) * Sdim + s) * 64 + c) = v0;
            *(float2*)(g_KV + ((size_t)(i0 + r0 + 8) * Sdim + s) * 64 + c) = v1;
        }
        __syncthreads();
    }

#pragma unroll 4
    for (int j = 0; j < 32; ++j) {
        int c = 8 * j + 2 * q;
        atomicAdd(&g_Xsum[(i0 + r) * 256 + c],     xa[2 * j]);
        atomicAdd(&g_Xsum[(i0 + r) * 256 + c + 1], xa[2 * j + 1]);
    }
}

// ================= pass 2q: Qbar = (Xsum/S) @ Wq, grid (64,8) =================
__global__ __launch_bounds__(256)
void pass2q_kernel(const float* __restrict__ Wq) {
    extern __shared__ float sm[];
    float* xbt = sm;            // 8*256
    float* wqs = sm + 2048;     // 256*32

    const int tid = threadIdx.x;
    const int i0 = blockIdx.x * 8, n0 = blockIdx.y * 32;

    for (int idx = tid; idx < 2048; idx += 256)
        xbt[idx] = g_Xsum[i0 * 256 + idx] * (1.f / (float)Sdim);
    for (int idx = tid; idx < 2048; idx += 256) {
        int kk = idx >> 3, c4 = idx & 7;
        ((float4*)(wqs + kk * 32))[c4] = ((const float4*)(Wq + kk * 256 + n0))[c4];
    }
    __syncthreads();

    const int col = tid & 31, rr = tid >> 5;
    float a0 = 0.f;
#pragma unroll 8
    for (int kk = 0; kk < 256; ++kk)
        a0 += xbt[rr * 256 + kk] * wqs[kk * 32 + col];
    g_Qbar[(i0 + rr) * 256 + n0 + col] = a0;
}

// ================= pass 2a: attention per column (coalesced KV) =================
#define KVP 65
__global__ __launch_bounds__(256, 1)
void pass2a_kernel() {
    extern __shared__ float sm[];
    float* qb  = sm;
    float* kvs = sm + 256;
    float* sc  = kvs + 256 * KVP;

    const int i = blockIdx.x, tid = threadIdx.x;
    qb[tid] = g_Qbar[i * 256 + tid];

    const float4* src = (const float4*)(g_KV + (size_t)i * Sdim * 64);
    for (int idx = tid; idx < 256 * 16; idx += 256) {
        int t = idx >> 4, j4 = idx & 15;
        float4 v = src[idx];
        float* d = kvs + t * KVP + j4 * 4;
        d[0] = v.x; d[1] = v.y; d[2] = v.z; d[3] = v.w;
    }
    __syncthreads();

    const int h = tid >> 5, lt = tid & 31;
    float sv[8];
#pragma unroll
    for (int k = 0; k < 8; ++k) {
        int t = lt + 32 * k;
        float s = 0.f;
#pragma unroll
        for (int d = 0; d < 32; ++d) s += qb[h * 32 + d] * kvs[t * KVP + d];
        sv[k] = s * 0.17677669529663687f;
    }
    float mx = sv[0];
#pragma unroll
    for (int k = 1; k < 8; ++k) mx = fmaxf(mx, sv[k]);
#pragma unroll
    for (int off = 16; off > 0; off >>= 1) mx = fmaxf(mx, __shfl_xor_sync(0xffffffffu, mx, off));
    float sum = 0.f;
#pragma unroll
    for (int k = 0; k < 8; ++k) { sv[k] = __expf(sv[k] - mx); sum += sv[k]; }
#pragma unroll
    for (int off = 16; off > 0; off >>= 1) sum += __shfl_xor_sync(0xffffffffu, sum, off);
    float rinv = 1.f / sum;
#pragma unroll
    for (int k = 0; k < 8; ++k) sc[h * 256 + lt + 32 * k] = sv[k] * rinv;
    __syncthreads();

    const int d = tid & 31;
    float wacc = 0.f;
#pragma unroll 4
    for (int t = 0; t < 256; ++t) wacc += sc[h * 256 + t] * kvs[t * KVP + 32 + d];
    g_Wgt[(size_t)i * 256 + h * 32 + d] = wacc;
}

// ================= pass 2b: mma.sync fp16 (Wg GEMM + gate + Wo GEMM), xn pre-LN'd =================
#define SM_AH 512
#define SM_B  (512 + 16896)
#define SM2B_BYTES ((512 + 16896 + 2 * 9216) * 4)

__device__ __forceinline__ const uint4* chunk_src(int j) {
    int g = j >> 2, kc = j & 3;
    return (const uint4*)(g_B32hi + (g * 4 + kc) * 8192);
}

__device__ __forceinline__ void mma_pass(const uint32_t* __restrict__ A,
                                         const uint32_t* __restrict__ B,
                                         int kc, int m0, int n0, int gid, int tig,
                                         float acc[4][8][4]) {
#pragma unroll
    for (int s = 0; s < 4; ++s) {
        const int kpA = kc * 32 + s * 8 + tig;
        uint32_t a[4][4];
#pragma unroll
        for (int mi = 0; mi < 4; ++mi) {
            const uint32_t* Ar = A + (m0 + mi * 16 + gid) * APITCH + kpA;
            a[mi][0] = Ar[0];
            a[mi][1] = Ar[8 * APITCH];
            a[mi][2] = Ar[4];
            a[mi][3] = Ar[8 * APITCH + 4];
        }
#pragma unroll
        for (int ni = 0; ni < 8; ++ni) {
            const uint32_t* Br = B + (n0 + ni * 8 + gid) * BPITCH + s * 8 + tig;
            uint32_t b0 = Br[0], b1 = Br[4];
#pragma unroll
            for (int mi = 0; mi < 4; ++mi) {
                asm volatile(
                    "mma.sync.aligned.m16n8k16.row.col.f32.f16.f16.f32 "
                    "{%0,%1,%2,%3}, {%4,%5,%6,%7}, {%8,%9}, {%0,%1,%2,%3};"
                    : "+f"(acc[mi][ni][0]), "+f"(acc[mi][ni][1]),
                      "+f"(acc[mi][ni][2]), "+f"(acc[mi][ni][3])
                    : "r"(a[mi][0]), "r"(a[mi][1]), "r"(a[mi][2]), "r"(a[mi][3]),
                      "r"(b0), "r"(b1));
            }
        }
    }
}

__global__ __launch_bounds__(256, 1)
void pass2b_mma_kernel(const float* __restrict__ bg, const float* __restrict__ bo,
                       float* __restrict__ out) {
    extern __shared__ uint32_t smu[];
    float* fsm = (float*)smu;
    const int tid = threadIdx.x;
    const int wid = tid >> 5, lane = tid & 31;
    const int gid = lane >> 2, tig = lane & 3;
    const int m0 = (wid >> 2) * 64, n0 = (wid & 3) * 64;
    const size_t r0 = (size_t)blockIdx.x * 128;
    const int i0 = (int)(r0 % Idim);

    fsm[tid] = bg[tid];
    fsm[256 + tid] = bo[tid];

    // ---- A stage: coalesced copy of pre-LN'd fp16 xn tile ----
    {
        const uint4* xn = (const uint4*)(g_Xn + r0 * 128);
#pragma unroll
        for (int t = 0; t < 16; ++t) {
            int idx4 = tid + t * 256;
            int row = idx4 >> 5, c4 = idx4 & 31;
            *(uint4*)(smu + SM_AH + row * APITCH + c4 * 4) = xn[idx4];
        }
    }

    // ---- stage chunk 0 ----
    {
        const uint4* s = chunk_src(0);
        uint4* d = (uint4*)(smu + SM_B);
#pragma unroll
        for (int t = 0; t < 8; ++t) {
            int u = tid + t * 256;
            int n = u >> 3, kq = u & 7;
            d[n * 9 + kq] = s[u];
        }
    }
    __syncthreads();

    float acc[4][8][4] = {};
    int cur = 0;

    for (int j = 0; j < 8; ++j) {
        uint4 pf[8];
        if (j < 7) {
            const uint4* s = chunk_src(j + 1);
#pragma unroll
            for (int t = 0; t < 8; ++t) pf[t] = s[tid + t * 256];
        }
        const int kc = j & 3;
        const uint32_t* Bb = smu + SM_B + cur * 9216;
        mma_pass(smu + SM_AH, Bb, kc, m0, n0, gid, tig, acc);
        if (j < 7) {
            uint4* d = (uint4*)(smu + SM_B + (cur ^ 1) * 9216);
#pragma unroll
            for (int t = 0; t < 8; ++t) {
                int u = tid + t * 256;
                int n = u >> 3, kq = u & 7;
                d[n * 9 + kq] = pf[t];
            }
        }
        __syncthreads();
        cur ^= 1;

        if (j == 3) {
            // ---- epilogue 1: val = sigmoid(acc + bg) * wgt -> A (fp16) ----
#pragma unroll
            for (int mi = 0; mi < 4; ++mi) {
#pragma unroll
                for (int ni = 0; ni < 8; ++ni) {
                    int c = n0 + ni * 8 + tig * 2;
#pragma unroll
                    for (int half = 0; half < 2; ++half) {
                        int r = m0 + mi * 16 + gid + half * 8;
                        float2 w = *(const float2*)(g_Wgt + (size_t)(i0 + r) * 256 + c);
                        float t0 = acc[mi][ni][half * 2 + 0] + fsm[c];
                        float t1 = acc[mi][ni][half * 2 + 1] + fsm[c + 1];
                        float v0 = w.x / (1.f + __expf(-t0));
                        float v1 = w.y / (1.f + __expf(-t1));
                        smu[SM_AH + r * APITCH + (c >> 1)] = pack_f16(v0, v1);
                        acc[mi][ni][half * 2 + 0] = 0.f;
                        acc[mi][ni][half * 2 + 1] = 0.f;
                    }
                }
            }
            __syncthreads();
        }
    }

    // ---- epilogue 2: out = acc + bo ----
#pragma unroll
    for (int mi = 0; mi < 4; ++mi) {
#pragma unroll
        for (int ni = 0; ni < 8; ++ni) {
            int c = n0 + ni * 8 + tig * 2;
#pragma unroll
            for (int half = 0; half < 2; ++half) {
                int r = m0 + mi * 16 + gid + half * 8;
                float2 v;
                v.x = acc[mi][ni][half * 2 + 0] + fsm[256 + c];
                v.y = acc[mi][ni][half * 2 + 1] + fsm[256 + c + 1];
                *(float2*)(out + (r0 + r) * Cdim + c) = v;
            }
        }
    }
}

// ---------------- launch ----------------
extern "C" void kernel_launch(void* const* d_in, const int* in_sizes, int n_in,
                              void* d_out, int out_size) {
    const float* x     = (const float*)d_in[0];
    const float* gamma = (const float*)d_in[1];
    const float* beta  = (const float*)d_in[2];
    const float* Wq    = (const float*)d_in[3];
    const float* Wk    = (const float*)d_in[4];
    const float* Wv    = (const float*)d_in[5];
    const float* Wg    = (const float*)d_in[6];
    const float* bg    = (const float*)d_in[7];
    const float* Wo    = (const float*)d_in[8];
    const float* bo    = (const float*)d_in[9];
    float* out = (float*)d_out;

    const int SMEM1  = P1_SMEM_U32 * 4;
    const int SMEM2Q = (2048 + 256 * 32) * 4;
    const int SMEM2A = (256 + 256 * KVP + 8 * 256) * 4;

    cudaFuncSetAttribute(pass1_kernel,      cudaFuncAttributeMaxDynamicSharedMemorySize, SMEM1);
    cudaFuncSetAttribute(pass2q_kernel,     cudaFuncAttributeMaxDynamicSharedMemorySize, SMEM2Q);
    cudaFuncSetAttribute(pass2a_kernel,     cudaFuncAttributeMaxDynamicSharedMemorySize, SMEM2A);
    cudaFuncSetAttribute(pass2b_mma_kernel, cudaFuncAttributeMaxDynamicSharedMemorySize, SM2B_BYTES);

    prep_weights_kernel<<<256, 256>>>(Wg, Wo);
    prep_kv_kernel<<<32, 256>>>(Wk, Wv);
    pass1_kernel<<<dim3(Idim / 64, Sdim / 8), 256, SMEM1>>>(x, gamma, beta);
    pass2q_kernel<<<dim3(64, 8), 256, SMEM2Q>>>(Wq);
    pass2a_kernel<<<Idim, 256, SMEM2A>>>();
    pass2b_mma_kernel<<<SI / 128, 256, SM2B_BYTES>>>(bg, bo, out);
}